// round 1
// baseline (speedup 1.0000x reference)
#include <cuda_runtime.h>
#include <math.h>

#define DIM   1024
#define HEADS 16
#define BSZ   2
#define SEQ   2048
#define HD    64
#define ROWS  (BSZ*SEQ)   // 4096

// Scratch (device globals; allocation-free)
__device__ float g_qkv[(size_t)ROWS * 3 * DIM];   // 50.3 MB
__device__ float g_attn[(size_t)ROWS * DIM];      // 16.8 MB
__device__ float g_hid[(size_t)ROWS * 2 * DIM];   // 33.6 MB

// ---------------------------------------------------------------------------
// Tiled SGEMM: C[M,N] = A[M,K] @ B[K,N] (+bias) (+SiLU)
// BM=BN=128, BK=16, 256 threads, 8x8 per-thread microtile.
// All problem dims divide tile dims exactly (no guards).
// ---------------------------------------------------------------------------
template<int ACT>  // 0 = none, 1 = SiLU
__global__ __launch_bounds__(256, 2)
void sgemm_kernel(const float* __restrict__ A, const float* __restrict__ B,
                  const float* __restrict__ bias, float* __restrict__ C,
                  int M, int N, int K)
{
    __shared__ float As[16][132];  // [k][m], padded
    __shared__ float Bs[16][132];  // [k][n], padded

    const int tid = threadIdx.x;
    const int tx = tid & 15, ty = tid >> 4;
    const int bm = blockIdx.y * 128;
    const int bn = blockIdx.x * 128;

    float acc[8][8];
    #pragma unroll
    for (int i = 0; i < 8; i++)
        #pragma unroll
        for (int j = 0; j < 8; j++) acc[i][j] = 0.f;

    for (int k0 = 0; k0 < K; k0 += 16) {
        // Load A tile (128x16) transposed into As[k][m]
        #pragma unroll
        for (int i = 0; i < 2; i++) {
            int id = tid + i * 256;          // 0..511
            int r = id >> 2, cv = (id & 3) * 4;
            float4 v = *(const float4*)(A + (size_t)(bm + r) * K + k0 + cv);
            As[cv + 0][r] = v.x;
            As[cv + 1][r] = v.y;
            As[cv + 2][r] = v.z;
            As[cv + 3][r] = v.w;
        }
        // Load B tile (16x128) into Bs[k][n]
        #pragma unroll
        for (int i = 0; i < 2; i++) {
            int id = tid + i * 256;
            int r = id >> 5, cv = (id & 31) * 4;
            *(float4*)&Bs[r][cv] = *(const float4*)(B + (size_t)(k0 + r) * N + bn + cv);
        }
        __syncthreads();

        #pragma unroll
        for (int kk = 0; kk < 16; kk++) {
            float4 a0 = *(float4*)&As[kk][ty * 8];
            float4 a1 = *(float4*)&As[kk][ty * 8 + 4];
            float4 b0 = *(float4*)&Bs[kk][tx * 8];
            float4 b1 = *(float4*)&Bs[kk][tx * 8 + 4];
            float a[8] = {a0.x, a0.y, a0.z, a0.w, a1.x, a1.y, a1.z, a1.w};
            float b[8] = {b0.x, b0.y, b0.z, b0.w, b1.x, b1.y, b1.z, b1.w};
            #pragma unroll
            for (int i = 0; i < 8; i++)
                #pragma unroll
                for (int j = 0; j < 8; j++)
                    acc[i][j] += a[i] * b[j];
        }
        __syncthreads();
    }

    // Epilogue
    #pragma unroll
    for (int i = 0; i < 8; i++) {
        const int row = bm + ty * 8 + i;
        float* crow = C + (size_t)row * N + bn + tx * 8;
        float vals[8];
        #pragma unroll
        for (int j = 0; j < 8; j++) {
            float v = acc[i][j];
            if (bias) v += bias[bn + tx * 8 + j];
            if (ACT == 1) v = v / (1.f + __expf(-v));   // SiLU
            vals[j] = v;
        }
        *(float4*)(crow)     = make_float4(vals[0], vals[1], vals[2], vals[3]);
        *(float4*)(crow + 4) = make_float4(vals[4], vals[5], vals[6], vals[7]);
    }
}

// ---------------------------------------------------------------------------
// Flash attention: per block = (batch b, head h, 64 query rows).
// KV processed in tiles of 32. Online softmax. hd=64, scale=1/8.
// Thread layout 16x16: thread (tx,ty) owns S[ty*4..+4][tx*2..+2],
// O[ty*4..+4][tx*4..+4].
// ---------------------------------------------------------------------------
__global__ __launch_bounds__(256, 2)
void attn_kernel(const float* __restrict__ qkv,
                 const float* __restrict__ mask,
                 float* __restrict__ out)
{
    __shared__ float Qs[HD][65];   // transposed: Qs[d][qrow]
    __shared__ float Ks[HD][33];   // transposed: Ks[d][kcol]
    __shared__ float Vs[32][68];   // row-major:  Vs[kv][d]
    __shared__ float Ps[64][36];   // mask tile, then P tile: [qrow][kv]

    const int tid = threadIdx.x;
    const int tx = tid & 15, ty = tid >> 4;
    const int b = blockIdx.z, h = blockIdx.y;
    const int q0 = blockIdx.x * 64;
    const int row0 = ty * 4;
    const size_t ldq = 3 * DIM;

    const float* qbase = qkv + (size_t)(b * SEQ + q0) * ldq + h * HD;
    const float* kbase = qkv + (size_t)(b * SEQ) * ldq + DIM + h * HD;
    const float* vbase = kbase + DIM;

    // Load Q tile transposed (64 rows x 64 dims)
    for (int i = tid; i < 64 * 16; i += 256) {
        int r = i >> 4, cv = (i & 15) * 4;
        float4 v = *(const float4*)(qbase + (size_t)r * ldq + cv);
        Qs[cv + 0][r] = v.x;
        Qs[cv + 1][r] = v.y;
        Qs[cv + 2][r] = v.z;
        Qs[cv + 3][r] = v.w;
    }

    float m[4], l[4], o[4][4];
    #pragma unroll
    for (int r = 0; r < 4; r++) {
        m[r] = -1e30f; l[r] = 0.f;
        #pragma unroll
        for (int c = 0; c < 4; c++) o[r][c] = 0.f;
    }

    for (int kv0 = 0; kv0 < SEQ; kv0 += 32) {
        __syncthreads();   // previous iteration done reading Ks/Vs/Ps

        // K tile transposed (32 x 64)
        for (int i = tid; i < 32 * 16; i += 256) {
            int r = i >> 4, cv = (i & 15) * 4;
            float4 v = *(const float4*)(kbase + (size_t)(kv0 + r) * ldq + cv);
            Ks[cv + 0][r] = v.x;
            Ks[cv + 1][r] = v.y;
            Ks[cv + 2][r] = v.z;
            Ks[cv + 3][r] = v.w;
        }
        // V tile row-major (32 x 64)
        for (int i = tid; i < 32 * 16; i += 256) {
            int r = i >> 4, cv = (i & 15) * 4;
            *(float4*)&Vs[r][cv] = *(const float4*)(vbase + (size_t)(kv0 + r) * ldq + cv);
        }
        // Mask tile (64 x 32) into Ps
        for (int i = tid; i < 64 * 8; i += 256) {
            int r = i >> 3, cv = (i & 7) * 4;
            *(float4*)&Ps[r][cv] = *(const float4*)(mask + (size_t)(q0 + r) * SEQ + kv0 + cv);
        }
        __syncthreads();

        // S = Q K^T
        float s[4][2];
        #pragma unroll
        for (int r = 0; r < 4; r++) { s[r][0] = 0.f; s[r][1] = 0.f; }
        #pragma unroll 8
        for (int d = 0; d < HD; d++) {
            float k0v = Ks[d][tx * 2];
            float k1v = Ks[d][tx * 2 + 1];
            #pragma unroll
            for (int r = 0; r < 4; r++) {
                float qv = Qs[d][row0 + r];
                s[r][0] += qv * k0v;
                s[r][1] += qv * k1v;
            }
        }

        // scale + mask, online softmax update, write P (reuses mask slots)
        #pragma unroll
        for (int r = 0; r < 4; r++) {
            float s0 = s[r][0] * 0.125f + Ps[row0 + r][tx * 2];
            float s1 = s[r][1] * 0.125f + Ps[row0 + r][tx * 2 + 1];
            float mx = fmaxf(s0, s1);
            mx = fmaxf(mx, __shfl_xor_sync(0xffffffffu, mx, 1));
            mx = fmaxf(mx, __shfl_xor_sync(0xffffffffu, mx, 2));
            mx = fmaxf(mx, __shfl_xor_sync(0xffffffffu, mx, 4));
            mx = fmaxf(mx, __shfl_xor_sync(0xffffffffu, mx, 8));
            float mn = fmaxf(m[r], mx);
            float alpha = __expf(m[r] - mn);
            m[r] = mn;
            float p0 = __expf(s0 - mn);
            float p1 = __expf(s1 - mn);
            float rs = p0 + p1;
            rs += __shfl_xor_sync(0xffffffffu, rs, 1);
            rs += __shfl_xor_sync(0xffffffffu, rs, 2);
            rs += __shfl_xor_sync(0xffffffffu, rs, 4);
            rs += __shfl_xor_sync(0xffffffffu, rs, 8);
            l[r] = l[r] * alpha + rs;
            #pragma unroll
            for (int c = 0; c < 4; c++) o[r][c] *= alpha;
            Ps[row0 + r][tx * 2]     = p0;
            Ps[row0 + r][tx * 2 + 1] = p1;
        }
        __syncthreads();

        // O += P @ V
        #pragma unroll 4
        for (int j = 0; j < 32; j++) {
            float4 v = *(float4*)&Vs[j][tx * 4];
            #pragma unroll
            for (int r = 0; r < 4; r++) {
                float p = Ps[row0 + r][j];
                o[r][0] += p * v.x;
                o[r][1] += p * v.y;
                o[r][2] += p * v.z;
                o[r][3] += p * v.w;
            }
        }
    }

    // Write O / l to [bs*n, dim] layout
    #pragma unroll
    for (int r = 0; r < 4; r++) {
        float inv = 1.f / l[r];
        float4 v = make_float4(o[r][0] * inv, o[r][1] * inv,
                               o[r][2] * inv, o[r][3] * inv);
        *(float4*)(out + (size_t)(b * SEQ + q0 + row0 + r) * DIM + h * HD + tx * 4) = v;
    }
}

// ---------------------------------------------------------------------------
// Launch
// ---------------------------------------------------------------------------
extern "C" void kernel_launch(void* const* d_in, const int* in_sizes, int n_in,
                              void* d_out, int out_size)
{
    const float* seq   = (const float*)d_in[0];
    const float* amask = (const float*)d_in[1];
    const float* Wqkv  = (const float*)d_in[2];
    const float* W1    = (const float*)d_in[3];
    const float* b1    = (const float*)d_in[4];
    const float* W2    = (const float*)d_in[5];
    const float* b2    = (const float*)d_in[6];
    float* out = (float*)d_out;

    float *qkv, *attn, *hid;
    cudaGetSymbolAddress((void**)&qkv,  g_qkv);
    cudaGetSymbolAddress((void**)&attn, g_attn);
    cudaGetSymbolAddress((void**)&hid,  g_hid);

    // 1) QKV projection: [4096,1024] @ [1024,3072]
    {
        dim3 grid(3 * DIM / 128, ROWS / 128);   // 24 x 32
        sgemm_kernel<0><<<grid, 256>>>(seq, Wqkv, nullptr, qkv, ROWS, 3 * DIM, DIM);
    }
    // 2) Attention
    {
        dim3 grid(SEQ / 64, HEADS, BSZ);        // 32 x 16 x 2
        attn_kernel<<<grid, 256>>>(qkv, amask, attn);
    }
    // 3) FFN layer 1 + bias + SiLU: [4096,1024] @ [1024,2048]
    {
        dim3 grid(2 * DIM / 128, ROWS / 128);   // 16 x 32
        sgemm_kernel<1><<<grid, 256>>>(attn, W1, b1, hid, ROWS, 2 * DIM, DIM);
    }
    // 4) FFN layer 2 + bias: [4096,2048] @ [2048,1024]
    {
        dim3 grid(DIM / 128, ROWS / 128);       // 8 x 32
        sgemm_kernel<0><<<grid, 256>>>(hid, W2, b2, out, ROWS, DIM, 2 * DIM);
    }
}

// round 2
// speedup vs baseline: 1.0908x; 1.0908x over previous
#include <cuda_runtime.h>
#include <math.h>
#include <stdint.h>

#define DIM   1024
#define HEADS 16
#define BSZ   2
#define SEQ   2048
#define HD    64
#define ROWS  (BSZ*SEQ)   // 4096

// Scratch (device globals; allocation-free)
__device__ float g_qkv[(size_t)ROWS * 3 * DIM];
__device__ float g_attn[(size_t)ROWS * DIM];
__device__ float g_hid[(size_t)ROWS * 2 * DIM];

// ---------------------------------------------------------------------------
// cp.async helpers
// ---------------------------------------------------------------------------
__device__ __forceinline__ void cp16(void* smem_dst, const void* gmem_src) {
    uint32_t d = (uint32_t)__cvta_generic_to_shared(smem_dst);
    asm volatile("cp.async.cg.shared.global [%0], [%1], 16;\n" :: "r"(d), "l"(gmem_src));
}
#define CP_COMMIT() asm volatile("cp.async.commit_group;\n" ::: "memory")
#define CP_WAIT1()  asm volatile("cp.async.wait_group 1;\n" ::: "memory")

// ---------------------------------------------------------------------------
// Pipelined SGEMM: C[M,N] = A[M,K] @ B[K,N] (+bias)(+SiLU)
// BM=BN=128, BK=16, 256 threads, 8x8 microtile, 3-stage cp.async ring.
// A tile stored row-major As[m][16] (pad 20), consumed as float4 k-fragments.
// B tile stored Bs[k][128] (pad 132).
// ---------------------------------------------------------------------------
#define A_STRIDE 20
#define B_STRIDE 132
#define A_STAGE  (128 * A_STRIDE)   // 2560 floats
#define B_STAGE  (16 * B_STRIDE)    // 2112 floats
#define SGEMM_SMEM_BYTES (3 * (A_STAGE + B_STAGE) * 4)  // 56064

__device__ __forceinline__ void sgemm_load_tile(
    const float* __restrict__ A, const float* __restrict__ B,
    int K, int N, int bm, int bn, int k0,
    float* Asb, float* Bsb, int tid)
{
    #pragma unroll
    for (int i = 0; i < 2; i++) {
        int c = tid + i * 256;           // 0..511
        int r = c >> 2, q = (c & 3) * 4; // 128 rows x 4 quads
        cp16(Asb + r * A_STRIDE + q, A + (size_t)(bm + r) * K + k0 + q);
    }
    #pragma unroll
    for (int i = 0; i < 2; i++) {
        int c = tid + i * 256;
        int r = c >> 5, q = (c & 31) * 4; // 16 rows x 32 quads
        cp16(Bsb + r * B_STRIDE + q, B + (size_t)(k0 + r) * N + bn + q);
    }
}

template<int ACT>  // 0 = none, 1 = SiLU
__global__ __launch_bounds__(256, 2)
void sgemm_kernel(const float* __restrict__ A, const float* __restrict__ B,
                  const float* __restrict__ bias, float* __restrict__ C,
                  int M, int N, int K)
{
    extern __shared__ float smem[];
    float* As = smem;                 // 3 * A_STAGE
    float* Bs = smem + 3 * A_STAGE;   // 3 * B_STAGE

    const int tid = threadIdx.x;
    const int tx = tid & 15, ty = tid >> 4;
    const int bm = blockIdx.y * 128;
    const int bn = blockIdx.x * 128;

    float acc[8][8];
    #pragma unroll
    for (int i = 0; i < 8; i++)
        #pragma unroll
        for (int j = 0; j < 8; j++) acc[i][j] = 0.f;

    const int T = K / 16;
    sgemm_load_tile(A, B, K, N, bm, bn, 0,  As,           Bs,           tid); CP_COMMIT();
    sgemm_load_tile(A, B, K, N, bm, bn, 16, As + A_STAGE, Bs + B_STAGE, tid); CP_COMMIT();

    for (int t = 0; t < T; t++) {
        CP_WAIT1();
        __syncthreads();

        const float* Asb = As + (t % 3) * A_STAGE;
        const float* Bsb = Bs + (t % 3) * B_STAGE;

        #pragma unroll
        for (int kq = 0; kq < 4; kq++) {
            float4 a4[8];
            #pragma unroll
            for (int i = 0; i < 8; i++)
                a4[i] = *(const float4*)(Asb + (ty * 8 + i) * A_STRIDE + kq * 4);

            #pragma unroll
            for (int s = 0; s < 4; s++) {
                const float* brow = Bsb + (kq * 4 + s) * B_STRIDE;
                float4 b0 = *(const float4*)(brow + tx * 8);
                float4 b1 = *(const float4*)(brow + tx * 8 + 4);
                float bv[8] = {b0.x, b0.y, b0.z, b0.w, b1.x, b1.y, b1.z, b1.w};
                #pragma unroll
                for (int i = 0; i < 8; i++) {
                    float av = (s == 0) ? a4[i].x : (s == 1) ? a4[i].y
                             : (s == 2) ? a4[i].z : a4[i].w;
                    #pragma unroll
                    for (int j = 0; j < 8; j++)
                        acc[i][j] += av * bv[j];
                }
            }
        }

        int tn = t + 2;
        if (tn < T) {
            sgemm_load_tile(A, B, K, N, bm, bn, tn * 16,
                            As + (tn % 3) * A_STAGE, Bs + (tn % 3) * B_STAGE, tid);
        }
        CP_COMMIT();
    }

    // Epilogue
    #pragma unroll
    for (int i = 0; i < 8; i++) {
        const int row = bm + ty * 8 + i;
        float* crow = C + (size_t)row * N + bn + tx * 8;
        float vals[8];
        #pragma unroll
        for (int j = 0; j < 8; j++) {
            float v = acc[i][j];
            if (bias) v += bias[bn + tx * 8 + j];
            if (ACT == 1) v = v / (1.f + __expf(-v));
            vals[j] = v;
        }
        *(float4*)(crow)     = make_float4(vals[0], vals[1], vals[2], vals[3]);
        *(float4*)(crow + 4) = make_float4(vals[4], vals[5], vals[6], vals[7]);
    }
}

// ---------------------------------------------------------------------------
// Flash attention: block = (batch b, head h, 64 query rows), KV tile 64.
// 16x16 threads; thread owns S[4r][4c] and O[4r][4c]. Dynamic smem 69.6KB.
// ---------------------------------------------------------------------------
#define AT_STRIDE 68
#define ATTN_SMEM_BYTES (4 * 64 * AT_STRIDE * 4)  // 69632

__global__ __launch_bounds__(256)
void attn_kernel(const float* __restrict__ qkv,
                 const float* __restrict__ mask,
                 float* __restrict__ out)
{
    extern __shared__ float smem[];
    float* Qs = smem;                        // [d][q]   64 x 68
    float* Ks = Qs + 64 * AT_STRIDE;         // [d][kv]  64 x 68
    float* Vs = Ks + 64 * AT_STRIDE;         // [kv][d]  64 x 68
    float* Ps = Vs + 64 * AT_STRIDE;         // [q][kv]  64 x 68

    const int tid = threadIdx.x;
    const int tx = tid & 15, ty = tid >> 4;
    const int b = blockIdx.z, h = blockIdx.y;
    const int q0 = blockIdx.x * 64;
    const int row0 = ty * 4;
    const int col0 = tx * 4;
    const size_t ldq = 3 * DIM;

    const float* qbase = qkv + (size_t)(b * SEQ + q0) * ldq + h * HD;
    const float* kbase = qkv + (size_t)(b * SEQ) * ldq + DIM + h * HD;
    const float* vbase = kbase + DIM;

    // Q tile transposed (64 q x 64 d) -> Qs[d][q]
    for (int i = tid; i < 64 * 16; i += 256) {
        int r = i >> 4, cv = (i & 15) * 4;
        float4 v = *(const float4*)(qbase + (size_t)r * ldq + cv);
        Qs[(cv + 0) * AT_STRIDE + r] = v.x;
        Qs[(cv + 1) * AT_STRIDE + r] = v.y;
        Qs[(cv + 2) * AT_STRIDE + r] = v.z;
        Qs[(cv + 3) * AT_STRIDE + r] = v.w;
    }

    float m[4], l[4], o[4][4];
    #pragma unroll
    for (int r = 0; r < 4; r++) {
        m[r] = -1e30f; l[r] = 0.f;
        #pragma unroll
        for (int c = 0; c < 4; c++) o[r][c] = 0.f;
    }

    for (int kv0 = 0; kv0 < SEQ; kv0 += 64) {
        __syncthreads();   // prev iter done reading Ks/Vs/Ps (and Q visible, iter0)

        // K transposed -> Ks[d][kv]
        for (int i = tid; i < 64 * 16; i += 256) {
            int r = i >> 4, cv = (i & 15) * 4;
            float4 v = *(const float4*)(kbase + (size_t)(kv0 + r) * ldq + cv);
            Ks[(cv + 0) * AT_STRIDE + r] = v.x;
            Ks[(cv + 1) * AT_STRIDE + r] = v.y;
            Ks[(cv + 2) * AT_STRIDE + r] = v.z;
            Ks[(cv + 3) * AT_STRIDE + r] = v.w;
        }
        // V row-major -> Vs[kv][d]
        for (int i = tid; i < 64 * 16; i += 256) {
            int r = i >> 4, cv = (i & 15) * 4;
            *(float4*)&Vs[r * AT_STRIDE + cv] =
                *(const float4*)(vbase + (size_t)(kv0 + r) * ldq + cv);
        }
        // mask tile -> Ps[q][kv]
        for (int i = tid; i < 64 * 16; i += 256) {
            int r = i >> 4, cv = (i & 15) * 4;
            *(float4*)&Ps[r * AT_STRIDE + cv] =
                *(const float4*)(mask + (size_t)(q0 + r) * SEQ + kv0 + cv);
        }
        __syncthreads();

        // S = Q K^T  (4x4 per thread)
        float s[4][4];
        #pragma unroll
        for (int r = 0; r < 4; r++)
            #pragma unroll
            for (int c = 0; c < 4; c++) s[r][c] = 0.f;

        #pragma unroll 8
        for (int d = 0; d < HD; d++) {
            float4 q4 = *(const float4*)&Qs[d * AT_STRIDE + row0];
            float4 k4 = *(const float4*)&Ks[d * AT_STRIDE + col0];
            float qa[4] = {q4.x, q4.y, q4.z, q4.w};
            float ka[4] = {k4.x, k4.y, k4.z, k4.w};
            #pragma unroll
            for (int r = 0; r < 4; r++)
                #pragma unroll
                for (int c = 0; c < 4; c++)
                    s[r][c] += qa[r] * ka[c];
        }

        // softmax (online), write P into Ps (overwrites mask cells this thread owns)
        #pragma unroll
        for (int r = 0; r < 4; r++) {
            float4 mk = *(const float4*)&Ps[(row0 + r) * AT_STRIDE + col0];
            float sv[4];
            sv[0] = s[r][0] * 0.125f + mk.x;
            sv[1] = s[r][1] * 0.125f + mk.y;
            sv[2] = s[r][2] * 0.125f + mk.z;
            sv[3] = s[r][3] * 0.125f + mk.w;
            float mx = fmaxf(fmaxf(sv[0], sv[1]), fmaxf(sv[2], sv[3]));
            mx = fmaxf(mx, __shfl_xor_sync(0xffffffffu, mx, 1));
            mx = fmaxf(mx, __shfl_xor_sync(0xffffffffu, mx, 2));
            mx = fmaxf(mx, __shfl_xor_sync(0xffffffffu, mx, 4));
            mx = fmaxf(mx, __shfl_xor_sync(0xffffffffu, mx, 8));
            float mn = fmaxf(m[r], mx);
            float alpha = __expf(m[r] - mn);
            m[r] = mn;
            float p0 = __expf(sv[0] - mn);
            float p1 = __expf(sv[1] - mn);
            float p2 = __expf(sv[2] - mn);
            float p3 = __expf(sv[3] - mn);
            float rs = (p0 + p1) + (p2 + p3);
            rs += __shfl_xor_sync(0xffffffffu, rs, 1);
            rs += __shfl_xor_sync(0xffffffffu, rs, 2);
            rs += __shfl_xor_sync(0xffffffffu, rs, 4);
            rs += __shfl_xor_sync(0xffffffffu, rs, 8);
            l[r] = l[r] * alpha + rs;
            #pragma unroll
            for (int c = 0; c < 4; c++) o[r][c] *= alpha;
            *(float4*)&Ps[(row0 + r) * AT_STRIDE + col0] = make_float4(p0, p1, p2, p3);
        }
        __syncthreads();

        // O += P @ V  (float4 P rows, float4 V rows)
        #pragma unroll 4
        for (int j4 = 0; j4 < 64; j4 += 4) {
            float4 p4[4];
            #pragma unroll
            for (int r = 0; r < 4; r++)
                p4[r] = *(const float4*)&Ps[(row0 + r) * AT_STRIDE + j4];
            float4 v4[4];
            #pragma unroll
            for (int ss = 0; ss < 4; ss++)
                v4[ss] = *(const float4*)&Vs[(j4 + ss) * AT_STRIDE + col0];
            #pragma unroll
            for (int r = 0; r < 4; r++) {
                float pr[4] = {p4[r].x, p4[r].y, p4[r].z, p4[r].w};
                #pragma unroll
                for (int ss = 0; ss < 4; ss++) {
                    o[r][0] += pr[ss] * v4[ss].x;
                    o[r][1] += pr[ss] * v4[ss].y;
                    o[r][2] += pr[ss] * v4[ss].z;
                    o[r][3] += pr[ss] * v4[ss].w;
                }
            }
        }
    }

    // Write O / l
    #pragma unroll
    for (int r = 0; r < 4; r++) {
        float inv = 1.f / l[r];
        float4 v = make_float4(o[r][0] * inv, o[r][1] * inv,
                               o[r][2] * inv, o[r][3] * inv);
        *(float4*)(out + (size_t)(b * SEQ + q0 + row0 + r) * DIM + h * HD + col0) = v;
    }
}

// ---------------------------------------------------------------------------
// Launch
// ---------------------------------------------------------------------------
extern "C" void kernel_launch(void* const* d_in, const int* in_sizes, int n_in,
                              void* d_out, int out_size)
{
    const float* seq   = (const float*)d_in[0];
    const float* amask = (const float*)d_in[1];
    const float* Wqkv  = (const float*)d_in[2];
    const float* W1    = (const float*)d_in[3];
    const float* b1    = (const float*)d_in[4];
    const float* W2    = (const float*)d_in[5];
    const float* b2    = (const float*)d_in[6];
    float* out = (float*)d_out;

    float *qkv, *attn, *hid;
    cudaGetSymbolAddress((void**)&qkv,  g_qkv);
    cudaGetSymbolAddress((void**)&attn, g_attn);
    cudaGetSymbolAddress((void**)&hid,  g_hid);

    cudaFuncSetAttribute(sgemm_kernel<0>, cudaFuncAttributeMaxDynamicSharedMemorySize, SGEMM_SMEM_BYTES);
    cudaFuncSetAttribute(sgemm_kernel<1>, cudaFuncAttributeMaxDynamicSharedMemorySize, SGEMM_SMEM_BYTES);
    cudaFuncSetAttribute(attn_kernel,     cudaFuncAttributeMaxDynamicSharedMemorySize, ATTN_SMEM_BYTES);

    // 1) QKV projection: [4096,1024] @ [1024,3072]
    {
        dim3 grid(3 * DIM / 128, ROWS / 128);
        sgemm_kernel<0><<<grid, 256, SGEMM_SMEM_BYTES>>>(seq, Wqkv, nullptr, qkv, ROWS, 3 * DIM, DIM);
    }
    // 2) Attention
    {
        dim3 grid(SEQ / 64, HEADS, BSZ);
        attn_kernel<<<grid, 256, ATTN_SMEM_BYTES>>>(qkv, amask, attn);
    }
    // 3) FFN1 + bias + SiLU: [4096,1024] @ [1024,2048]
    {
        dim3 grid(2 * DIM / 128, ROWS / 128);
        sgemm_kernel<1><<<grid, 256, SGEMM_SMEM_BYTES>>>(attn, W1, b1, hid, ROWS, 2 * DIM, DIM);
    }
    // 4) FFN2 + bias: [4096,2048] @ [2048,1024]
    {
        dim3 grid(DIM / 128, ROWS / 128);
        sgemm_kernel<0><<<grid, 256, SGEMM_SMEM_BYTES>>>(hid, W2, b2, out, ROWS, DIM, 2 * DIM);
    }
}

// round 3
// speedup vs baseline: 1.7711x; 1.6237x over previous
#include <cuda_runtime.h>
#include <math.h>
#include <stdint.h>

#define DIM   1024
#define HEADS 16
#define BSZ   2
#define SEQ   2048
#define HD    64
#define ROWS  (BSZ*SEQ)   // 4096

// Scratch (device globals; allocation-free)
__device__ float g_qkv[(size_t)ROWS * 3 * DIM];
__device__ float g_attn[(size_t)ROWS * DIM];
__device__ float g_hid[(size_t)ROWS * 2 * DIM];

// ---------------------------------------------------------------------------
// helpers
// ---------------------------------------------------------------------------
__device__ __forceinline__ void cp16(void* smem_dst, const void* gmem_src) {
    uint32_t d = (uint32_t)__cvta_generic_to_shared(smem_dst);
    asm volatile("cp.async.cg.shared.global [%0], [%1], 16;\n" :: "r"(d), "l"(gmem_src));
}
#define CP_COMMIT() asm volatile("cp.async.commit_group;\n" ::: "memory")
#define CP_WAIT1()  asm volatile("cp.async.wait_group 1;\n" ::: "memory")

__device__ __forceinline__ uint32_t f2tf32(float x) {
    uint32_t r;
    asm("cvt.rna.tf32.f32 %0, %1;" : "=r"(r) : "f"(x));
    return r;
}

__device__ __forceinline__ void mma_tf32(float c[4], const uint32_t a[4], const uint32_t b[2]) {
    asm volatile(
        "mma.sync.aligned.m16n8k8.row.col.f32.tf32.tf32.f32 "
        "{%0,%1,%2,%3}, {%4,%5,%6,%7}, {%8,%9}, {%0,%1,%2,%3};\n"
        : "+f"(c[0]), "+f"(c[1]), "+f"(c[2]), "+f"(c[3])
        : "r"(a[0]), "r"(a[1]), "r"(a[2]), "r"(a[3]), "r"(b[0]), "r"(b[1]));
}

// ---------------------------------------------------------------------------
// tf32 tensor-core GEMM: C[M,N] = A[M,K] @ B[K,N] (+bias)(+SiLU)
// BM=BN=128, BK=32, 256 threads (8 warps as 2m x 4n), warp tile 64x32.
// Per warp: 4 m-tiles (m16) x 4 n-tiles (n8), k in steps of 8.
// A smem [m][k] stride 36 (==4 mod 32: conflict-free fragment loads).
// B smem [k][n] stride 136 (==8 mod 32: conflict-free fragment loads).
// 3-stage cp.async ring.
// ---------------------------------------------------------------------------
#define AS_STRIDE 36
#define BS_STRIDE 136
#define A_STAGE (128 * AS_STRIDE)   // 4608 floats
#define B_STAGE (32 * BS_STRIDE)    // 4352 floats
#define GEMM_SMEM_BYTES (3 * (A_STAGE + B_STAGE) * 4)  // 107520

__device__ __forceinline__ void gemm_load_tile(
    const float* __restrict__ A, const float* __restrict__ B,
    int K, int N, int bm, int bn, int k0,
    float* Asb, float* Bsb, int tid)
{
    #pragma unroll
    for (int i = 0; i < 4; i++) {
        int id = tid + i * 256;                 // 0..1023
        int rA = id >> 3, qA = (id & 7) * 4;    // 128 rows x 8 quads
        cp16(Asb + rA * AS_STRIDE + qA, A + (size_t)(bm + rA) * K + k0 + qA);
        int rB = id >> 5, qB = (id & 31) * 4;   // 32 rows x 32 quads
        cp16(Bsb + rB * BS_STRIDE + qB, B + (size_t)(k0 + rB) * N + bn + qB);
    }
}

template<int ACT>  // 0 = none, 1 = SiLU
__global__ __launch_bounds__(256, 2)
void tgemm_kernel(const float* __restrict__ A, const float* __restrict__ B,
                  const float* __restrict__ bias, float* __restrict__ C,
                  int M, int N, int K)
{
    extern __shared__ float smem[];
    float* As = smem;
    float* Bs = smem + 3 * A_STAGE;

    const int tid  = threadIdx.x;
    const int lane = tid & 31;
    const int wid  = tid >> 5;
    const int gid  = lane >> 2;   // 0..7
    const int tig  = lane & 3;    // 0..3
    const int warp_m = wid & 1;   // 0..1
    const int warp_n = wid >> 1;  // 0..3
    const int bm = blockIdx.y * 128;
    const int bn = blockIdx.x * 128;

    float acc[4][4][4];
    #pragma unroll
    for (int mt = 0; mt < 4; mt++)
        #pragma unroll
        for (int nt = 0; nt < 4; nt++)
            #pragma unroll
            for (int r = 0; r < 4; r++) acc[mt][nt][r] = 0.f;

    const int T = K / 32;
    gemm_load_tile(A, B, K, N, bm, bn, 0,  As,           Bs,           tid); CP_COMMIT();
    gemm_load_tile(A, B, K, N, bm, bn, 32, As + A_STAGE, Bs + B_STAGE, tid); CP_COMMIT();

    const int a_row0 = warp_m * 64 + gid;
    const int b_col0 = warp_n * 32 + gid;

    for (int t = 0; t < T; t++) {
        CP_WAIT1();
        __syncthreads();

        int tn = t + 2;
        if (tn < T) {
            gemm_load_tile(A, B, K, N, bm, bn, tn * 32,
                           As + (tn % 3) * A_STAGE, Bs + (tn % 3) * B_STAGE, tid);
        }
        CP_COMMIT();

        const float* Asb = As + (t % 3) * A_STAGE;
        const float* Bsb = Bs + (t % 3) * B_STAGE;

        #pragma unroll
        for (int kq = 0; kq < 4; kq++) {
            const int k0s = kq * 8;
            uint32_t af[4][4];
            #pragma unroll
            for (int mt = 0; mt < 4; mt++) {
                const float* ap = Asb + (a_row0 + mt * 16) * AS_STRIDE + k0s + tig;
                af[mt][0] = f2tf32(ap[0]);
                af[mt][1] = f2tf32(ap[8 * AS_STRIDE]);
                af[mt][2] = f2tf32(ap[4]);
                af[mt][3] = f2tf32(ap[8 * AS_STRIDE + 4]);
            }
            uint32_t bf[4][2];
            #pragma unroll
            for (int nt = 0; nt < 4; nt++) {
                const float* bp = Bsb + (k0s + tig) * BS_STRIDE + b_col0 + nt * 8;
                bf[nt][0] = f2tf32(bp[0]);
                bf[nt][1] = f2tf32(bp[4 * BS_STRIDE]);
            }
            #pragma unroll
            for (int mt = 0; mt < 4; mt++)
                #pragma unroll
                for (int nt = 0; nt < 4; nt++)
                    mma_tf32(acc[mt][nt], af[mt], bf[nt]);
        }
    }

    // Epilogue: c0/c1 at (row, 2*tig), c2/c3 at (row+8, 2*tig)
    #pragma unroll
    for (int mt = 0; mt < 4; mt++) {
        const int r0 = bm + warp_m * 64 + mt * 16 + gid;
        #pragma unroll
        for (int nt = 0; nt < 4; nt++) {
            const int c0 = bn + warp_n * 32 + nt * 8 + tig * 2;
            float b0 = 0.f, b1 = 0.f;
            if (bias) { b0 = bias[c0]; b1 = bias[c0 + 1]; }
            float v0 = acc[mt][nt][0] + b0;
            float v1 = acc[mt][nt][1] + b1;
            float v2 = acc[mt][nt][2] + b0;
            float v3 = acc[mt][nt][3] + b1;
            if (ACT == 1) {
                v0 = v0 / (1.f + __expf(-v0));
                v1 = v1 / (1.f + __expf(-v1));
                v2 = v2 / (1.f + __expf(-v2));
                v3 = v3 / (1.f + __expf(-v3));
            }
            *(float2*)(C + (size_t)r0 * N + c0)       = make_float2(v0, v1);
            *(float2*)(C + (size_t)(r0 + 8) * N + c0) = make_float2(v2, v3);
        }
    }
}

// ---------------------------------------------------------------------------
// Flash attention (unchanged from R2): block = (b, h, 64 q rows), KV tile 64.
// ---------------------------------------------------------------------------
#define AT_STRIDE 68
#define ATTN_SMEM_BYTES (4 * 64 * AT_STRIDE * 4)  // 69632

__global__ __launch_bounds__(256)
void attn_kernel(const float* __restrict__ qkv,
                 const float* __restrict__ mask,
                 float* __restrict__ out)
{
    extern __shared__ float smem[];
    float* Qs = smem;
    float* Ks = Qs + 64 * AT_STRIDE;
    float* Vs = Ks + 64 * AT_STRIDE;
    float* Ps = Vs + 64 * AT_STRIDE;

    const int tid = threadIdx.x;
    const int tx = tid & 15, ty = tid >> 4;
    const int b = blockIdx.z, h = blockIdx.y;
    const int q0 = blockIdx.x * 64;
    const int row0 = ty * 4;
    const int col0 = tx * 4;
    const size_t ldq = 3 * DIM;

    const float* qbase = qkv + (size_t)(b * SEQ + q0) * ldq + h * HD;
    const float* kbase = qkv + (size_t)(b * SEQ) * ldq + DIM + h * HD;
    const float* vbase = kbase + DIM;

    for (int i = tid; i < 64 * 16; i += 256) {
        int r = i >> 4, cv = (i & 15) * 4;
        float4 v = *(const float4*)(qbase + (size_t)r * ldq + cv);
        Qs[(cv + 0) * AT_STRIDE + r] = v.x;
        Qs[(cv + 1) * AT_STRIDE + r] = v.y;
        Qs[(cv + 2) * AT_STRIDE + r] = v.z;
        Qs[(cv + 3) * AT_STRIDE + r] = v.w;
    }

    float m[4], l[4], o[4][4];
    #pragma unroll
    for (int r = 0; r < 4; r++) {
        m[r] = -1e30f; l[r] = 0.f;
        #pragma unroll
        for (int c = 0; c < 4; c++) o[r][c] = 0.f;
    }

    for (int kv0 = 0; kv0 < SEQ; kv0 += 64) {
        __syncthreads();

        for (int i = tid; i < 64 * 16; i += 256) {
            int r = i >> 4, cv = (i & 15) * 4;
            float4 v = *(const float4*)(kbase + (size_t)(kv0 + r) * ldq + cv);
            Ks[(cv + 0) * AT_STRIDE + r] = v.x;
            Ks[(cv + 1) * AT_STRIDE + r] = v.y;
            Ks[(cv + 2) * AT_STRIDE + r] = v.z;
            Ks[(cv + 3) * AT_STRIDE + r] = v.w;
        }
        for (int i = tid; i < 64 * 16; i += 256) {
            int r = i >> 4, cv = (i & 15) * 4;
            *(float4*)&Vs[r * AT_STRIDE + cv] =
                *(const float4*)(vbase + (size_t)(kv0 + r) * ldq + cv);
        }
        for (int i = tid; i < 64 * 16; i += 256) {
            int r = i >> 4, cv = (i & 15) * 4;
            *(float4*)&Ps[r * AT_STRIDE + cv] =
                *(const float4*)(mask + (size_t)(q0 + r) * SEQ + kv0 + cv);
        }
        __syncthreads();

        float s[4][4];
        #pragma unroll
        for (int r = 0; r < 4; r++)
            #pragma unroll
            for (int c = 0; c < 4; c++) s[r][c] = 0.f;

        #pragma unroll 8
        for (int d = 0; d < HD; d++) {
            float4 q4 = *(const float4*)&Qs[d * AT_STRIDE + row0];
            float4 k4 = *(const float4*)&Ks[d * AT_STRIDE + col0];
            float qa[4] = {q4.x, q4.y, q4.z, q4.w};
            float ka[4] = {k4.x, k4.y, k4.z, k4.w};
            #pragma unroll
            for (int r = 0; r < 4; r++)
                #pragma unroll
                for (int c = 0; c < 4; c++)
                    s[r][c] += qa[r] * ka[c];
        }

        #pragma unroll
        for (int r = 0; r < 4; r++) {
            float4 mk = *(const float4*)&Ps[(row0 + r) * AT_STRIDE + col0];
            float sv[4];
            sv[0] = s[r][0] * 0.125f + mk.x;
            sv[1] = s[r][1] * 0.125f + mk.y;
            sv[2] = s[r][2] * 0.125f + mk.z;
            sv[3] = s[r][3] * 0.125f + mk.w;
            float mx = fmaxf(fmaxf(sv[0], sv[1]), fmaxf(sv[2], sv[3]));
            mx = fmaxf(mx, __shfl_xor_sync(0xffffffffu, mx, 1));
            mx = fmaxf(mx, __shfl_xor_sync(0xffffffffu, mx, 2));
            mx = fmaxf(mx, __shfl_xor_sync(0xffffffffu, mx, 4));
            mx = fmaxf(mx, __shfl_xor_sync(0xffffffffu, mx, 8));
            float mn = fmaxf(m[r], mx);
            float alpha = __expf(m[r] - mn);
            m[r] = mn;
            float p0 = __expf(sv[0] - mn);
            float p1 = __expf(sv[1] - mn);
            float p2 = __expf(sv[2] - mn);
            float p3 = __expf(sv[3] - mn);
            float rs = (p0 + p1) + (p2 + p3);
            rs += __shfl_xor_sync(0xffffffffu, rs, 1);
            rs += __shfl_xor_sync(0xffffffffu, rs, 2);
            rs += __shfl_xor_sync(0xffffffffu, rs, 4);
            rs += __shfl_xor_sync(0xffffffffu, rs, 8);
            l[r] = l[r] * alpha + rs;
            #pragma unroll
            for (int c = 0; c < 4; c++) o[r][c] *= alpha;
            *(float4*)&Ps[(row0 + r) * AT_STRIDE + col0] = make_float4(p0, p1, p2, p3);
        }
        __syncthreads();

        #pragma unroll 4
        for (int j4 = 0; j4 < 64; j4 += 4) {
            float4 p4[4];
            #pragma unroll
            for (int r = 0; r < 4; r++)
                p4[r] = *(const float4*)&Ps[(row0 + r) * AT_STRIDE + j4];
            float4 v4[4];
            #pragma unroll
            for (int ss = 0; ss < 4; ss++)
                v4[ss] = *(const float4*)&Vs[(j4 + ss) * AT_STRIDE + col0];
            #pragma unroll
            for (int r = 0; r < 4; r++) {
                float pr[4] = {p4[r].x, p4[r].y, p4[r].z, p4[r].w};
                #pragma unroll
                for (int ss = 0; ss < 4; ss++) {
                    o[r][0] += pr[ss] * v4[ss].x;
                    o[r][1] += pr[ss] * v4[ss].y;
                    o[r][2] += pr[ss] * v4[ss].z;
                    o[r][3] += pr[ss] * v4[ss].w;
                }
            }
        }
    }

    #pragma unroll
    for (int r = 0; r < 4; r++) {
        float inv = 1.f / l[r];
        float4 v = make_float4(o[r][0] * inv, o[r][1] * inv,
                               o[r][2] * inv, o[r][3] * inv);
        *(float4*)(out + (size_t)(b * SEQ + q0 + row0 + r) * DIM + h * HD + col0) = v;
    }
}

// ---------------------------------------------------------------------------
// Launch
// ---------------------------------------------------------------------------
extern "C" void kernel_launch(void* const* d_in, const int* in_sizes, int n_in,
                              void* d_out, int out_size)
{
    const float* seq   = (const float*)d_in[0];
    const float* amask = (const float*)d_in[1];
    const float* Wqkv  = (const float*)d_in[2];
    const float* W1    = (const float*)d_in[3];
    const float* b1    = (const float*)d_in[4];
    const float* W2    = (const float*)d_in[5];
    const float* b2    = (const float*)d_in[6];
    float* out = (float*)d_out;

    float *qkv, *attn, *hid;
    cudaGetSymbolAddress((void**)&qkv,  g_qkv);
    cudaGetSymbolAddress((void**)&attn, g_attn);
    cudaGetSymbolAddress((void**)&hid,  g_hid);

    cudaFuncSetAttribute(tgemm_kernel<0>, cudaFuncAttributeMaxDynamicSharedMemorySize, GEMM_SMEM_BYTES);
    cudaFuncSetAttribute(tgemm_kernel<1>, cudaFuncAttributeMaxDynamicSharedMemorySize, GEMM_SMEM_BYTES);
    cudaFuncSetAttribute(attn_kernel,     cudaFuncAttributeMaxDynamicSharedMemorySize, ATTN_SMEM_BYTES);

    // 1) QKV projection: [4096,1024] @ [1024,3072]
    {
        dim3 grid(3 * DIM / 128, ROWS / 128);
        tgemm_kernel<0><<<grid, 256, GEMM_SMEM_BYTES>>>(seq, Wqkv, nullptr, qkv, ROWS, 3 * DIM, DIM);
    }
    // 2) Attention
    {
        dim3 grid(SEQ / 64, HEADS, BSZ);
        attn_kernel<<<grid, 256, ATTN_SMEM_BYTES>>>(qkv, amask, attn);
    }
    // 3) FFN1 + bias + SiLU: [4096,1024] @ [1024,2048]
    {
        dim3 grid(2 * DIM / 128, ROWS / 128);
        tgemm_kernel<1><<<grid, 256, GEMM_SMEM_BYTES>>>(attn, W1, b1, hid, ROWS, 2 * DIM, DIM);
    }
    // 4) FFN2 + bias: [4096,2048] @ [2048,1024]
    {
        dim3 grid(DIM / 128, ROWS / 128);
        tgemm_kernel<0><<<grid, 256, GEMM_SMEM_BYTES>>>(hid, W2, b2, out, ROWS, DIM, 2 * DIM);
    }
}

// round 4
// speedup vs baseline: 2.8273x; 1.5964x over previous
#include <cuda_runtime.h>
#include <math.h>
#include <stdint.h>

#define DIM   1024
#define HEADS 16
#define BSZ   2
#define SEQ   2048
#define HD    64
#define ROWS  (BSZ*SEQ)   // 4096

// Scratch (device globals; allocation-free)
__device__ float g_qkv[(size_t)ROWS * 3 * DIM];
__device__ float g_attn[(size_t)ROWS * DIM];
__device__ float g_hid[(size_t)ROWS * 2 * DIM];

// ---------------------------------------------------------------------------
// helpers
// ---------------------------------------------------------------------------
__device__ __forceinline__ void cp16(void* smem_dst, const void* gmem_src) {
    uint32_t d = (uint32_t)__cvta_generic_to_shared(smem_dst);
    asm volatile("cp.async.cg.shared.global [%0], [%1], 16;\n" :: "r"(d), "l"(gmem_src));
}
#define CP_COMMIT() asm volatile("cp.async.commit_group;\n" ::: "memory")
#define CP_WAIT1()  asm volatile("cp.async.wait_group 1;\n" ::: "memory")

__device__ __forceinline__ uint32_t f2tf32(float x) {
    uint32_t r;
    asm("cvt.rna.tf32.f32 %0, %1;" : "=r"(r) : "f"(x));
    return r;
}

__device__ __forceinline__ void mma_tf32(float c[4], const uint32_t a[4], const uint32_t b[2]) {
    asm volatile(
        "mma.sync.aligned.m16n8k8.row.col.f32.tf32.tf32.f32 "
        "{%0,%1,%2,%3}, {%4,%5,%6,%7}, {%8,%9}, {%0,%1,%2,%3};\n"
        : "+f"(c[0]), "+f"(c[1]), "+f"(c[2]), "+f"(c[3])
        : "r"(a[0]), "r"(a[1]), "r"(a[2]), "r"(a[3]), "r"(b[0]), "r"(b[1]));
}

// ---------------------------------------------------------------------------
// tf32 tensor-core GEMM (unchanged from R3)
// ---------------------------------------------------------------------------
#define AS_STRIDE 36
#define BS_STRIDE 136
#define A_STAGE (128 * AS_STRIDE)
#define B_STAGE (32 * BS_STRIDE)
#define GEMM_SMEM_BYTES (3 * (A_STAGE + B_STAGE) * 4)  // 107520

__device__ __forceinline__ void gemm_load_tile(
    const float* __restrict__ A, const float* __restrict__ B,
    int K, int N, int bm, int bn, int k0,
    float* Asb, float* Bsb, int tid)
{
    #pragma unroll
    for (int i = 0; i < 4; i++) {
        int id = tid + i * 256;
        int rA = id >> 3, qA = (id & 7) * 4;
        cp16(Asb + rA * AS_STRIDE + qA, A + (size_t)(bm + rA) * K + k0 + qA);
        int rB = id >> 5, qB = (id & 31) * 4;
        cp16(Bsb + rB * BS_STRIDE + qB, B + (size_t)(k0 + rB) * N + bn + qB);
    }
}

template<int ACT>
__global__ __launch_bounds__(256, 2)
void tgemm_kernel(const float* __restrict__ A, const float* __restrict__ B,
                  const float* __restrict__ bias, float* __restrict__ C,
                  int M, int N, int K)
{
    extern __shared__ float smem[];
    float* As = smem;
    float* Bs = smem + 3 * A_STAGE;

    const int tid  = threadIdx.x;
    const int lane = tid & 31;
    const int wid  = tid >> 5;
    const int gid  = lane >> 2;
    const int tig  = lane & 3;
    const int warp_m = wid & 1;
    const int warp_n = wid >> 1;
    const int bm = blockIdx.y * 128;
    const int bn = blockIdx.x * 128;

    float acc[4][4][4];
    #pragma unroll
    for (int mt = 0; mt < 4; mt++)
        #pragma unroll
        for (int nt = 0; nt < 4; nt++)
            #pragma unroll
            for (int r = 0; r < 4; r++) acc[mt][nt][r] = 0.f;

    const int T = K / 32;
    gemm_load_tile(A, B, K, N, bm, bn, 0,  As,           Bs,           tid); CP_COMMIT();
    gemm_load_tile(A, B, K, N, bm, bn, 32, As + A_STAGE, Bs + B_STAGE, tid); CP_COMMIT();

    const int a_row0 = warp_m * 64 + gid;
    const int b_col0 = warp_n * 32 + gid;

    for (int t = 0; t < T; t++) {
        CP_WAIT1();
        __syncthreads();

        int tn = t + 2;
        if (tn < T) {
            gemm_load_tile(A, B, K, N, bm, bn, tn * 32,
                           As + (tn % 3) * A_STAGE, Bs + (tn % 3) * B_STAGE, tid);
        }
        CP_COMMIT();

        const float* Asb = As + (t % 3) * A_STAGE;
        const float* Bsb = Bs + (t % 3) * B_STAGE;

        #pragma unroll
        for (int kq = 0; kq < 4; kq++) {
            const int k0s = kq * 8;
            uint32_t af[4][4];
            #pragma unroll
            for (int mt = 0; mt < 4; mt++) {
                const float* ap = Asb + (a_row0 + mt * 16) * AS_STRIDE + k0s + tig;
                af[mt][0] = f2tf32(ap[0]);
                af[mt][1] = f2tf32(ap[8 * AS_STRIDE]);
                af[mt][2] = f2tf32(ap[4]);
                af[mt][3] = f2tf32(ap[8 * AS_STRIDE + 4]);
            }
            uint32_t bf[4][2];
            #pragma unroll
            for (int nt = 0; nt < 4; nt++) {
                const float* bp = Bsb + (k0s + tig) * BS_STRIDE + b_col0 + nt * 8;
                bf[nt][0] = f2tf32(bp[0]);
                bf[nt][1] = f2tf32(bp[4 * BS_STRIDE]);
            }
            #pragma unroll
            for (int mt = 0; mt < 4; mt++)
                #pragma unroll
                for (int nt = 0; nt < 4; nt++)
                    mma_tf32(acc[mt][nt], af[mt], bf[nt]);
        }
    }

    #pragma unroll
    for (int mt = 0; mt < 4; mt++) {
        const int r0 = bm + warp_m * 64 + mt * 16 + gid;
        #pragma unroll
        for (int nt = 0; nt < 4; nt++) {
            const int c0 = bn + warp_n * 32 + nt * 8 + tig * 2;
            float b0 = 0.f, b1 = 0.f;
            if (bias) { b0 = bias[c0]; b1 = bias[c0 + 1]; }
            float v0 = acc[mt][nt][0] + b0;
            float v1 = acc[mt][nt][1] + b1;
            float v2 = acc[mt][nt][2] + b0;
            float v3 = acc[mt][nt][3] + b1;
            if (ACT == 1) {
                v0 = v0 / (1.f + __expf(-v0));
                v1 = v1 / (1.f + __expf(-v1));
                v2 = v2 / (1.f + __expf(-v2));
                v3 = v3 / (1.f + __expf(-v3));
            }
            *(float2*)(C + (size_t)r0 * N + c0)       = make_float2(v0, v1);
            *(float2*)(C + (size_t)(r0 + 8) * N + c0) = make_float2(v2, v3);
        }
    }
}

// ---------------------------------------------------------------------------
// tf32 tensor-core flash attention.
// Block = (b, h, 128 q rows). 8 warps; warp w owns q rows [w*16, w*16+16).
// KV tile 64, 2-stage cp.async ring. S and PV via mma.m16n8k8.tf32.
// All smem tiles natural row-major; fragment strides 68 (==4 mod 32).
// Q staged once -> register fragments; Q smem reused as P buffer (per-warp
// private rows => only __syncwarp between P store and PV fragment loads).
// Mask read directly from gmem (L2-resident).
// ---------------------------------------------------------------------------
#define ATS 68
#define KV_STAGE (2 * 64 * ATS)               // K + V, one stage, floats (8704)
#define ATTN_SMEM_FLOATS (128 * ATS + 2 * KV_STAGE)
#define ATTN_SMEM_BYTES  (ATTN_SMEM_FLOATS * 4)   // 104448

__device__ __forceinline__ void attn_load_kv(
    const float* kbase, const float* vbase, int kv0,
    float* Kst, float* Vst, int tid)
{
    #pragma unroll
    for (int i = 0; i < 4; i++) {
        int c = tid + i * 256;            // 0..1023
        int r = c >> 4, q = (c & 15) * 4; // 64 rows x 16 quads
        cp16(Kst + r * ATS + q, kbase + (size_t)(kv0 + r) * (3 * DIM) + q);
        cp16(Vst + r * ATS + q, vbase + (size_t)(kv0 + r) * (3 * DIM) + q);
    }
}

__global__ __launch_bounds__(256)
void attn_kernel(const float* __restrict__ qkv,
                 const float* __restrict__ mask,
                 float* __restrict__ out)
{
    extern __shared__ float smem[];
    float* Ps = smem;                 // 128 x 68 : Q staging, then P
    float* KV = smem + 128 * ATS;     // 2 stages of (K 64x68 + V 64x68)

    const int tid  = threadIdx.x;
    const int lane = tid & 31;
    const int w    = tid >> 5;        // warp 0..7
    const int gid  = lane >> 2;       // 0..7
    const int tig  = lane & 3;        // 0..3
    const int bb = blockIdx.z, h = blockIdx.y;
    const int q0 = blockIdx.x * 128;
    const size_t ldq = 3 * DIM;

    const float* qbase = qkv + (size_t)(bb * SEQ + q0) * ldq + h * HD;
    const float* kbase = qkv + (size_t)(bb * SEQ) * ldq + DIM + h * HD;
    const float* vbase = kbase + DIM;

    // Prologue: stage Q (128x64) and KV tile 0
    #pragma unroll
    for (int i = 0; i < 8; i++) {
        int c = tid + i * 256;            // 0..2047
        int r = c >> 4, q = (c & 15) * 4;
        cp16(Ps + r * ATS + q, qbase + (size_t)r * ldq + q);
    }
    attn_load_kv(kbase, vbase, 0, KV, KV + 64 * ATS, tid);
    CP_COMMIT();

    uint32_t qf[8][4];
    float oacc[8][4];
    #pragma unroll
    for (int nt = 0; nt < 8; nt++)
        #pragma unroll
        for (int r = 0; r < 4; r++) oacc[nt][r] = 0.f;
    float mrow0 = -1e30f, mrow1 = -1e30f, lrow0 = 0.f, lrow1 = 0.f;

    const int qrow = w * 16 + gid;             // local row (c0/c1); +8 for c2/c3
    const int Rg = q0 + qrow;                  // global q row

    const int NT = SEQ / 64;                   // 32 kv tiles
    for (int t = 0; t < NT; t++) {
        const int cur = t & 1;
        if (t + 1 < NT) {
            float* Kn = KV + ((t + 1) & 1) * KV_STAGE;
            attn_load_kv(kbase, vbase, (t + 1) * 64, Kn, Kn + 64 * ATS, tid);
        }
        CP_COMMIT();
        CP_WAIT1();
        __syncthreads();

        if (t == 0) {
            // extract Q fragments (rows of this warp), then Ps becomes P buffer
            #pragma unroll
            for (int kt = 0; kt < 8; kt++) {
                const float* ap = Ps + qrow * ATS + kt * 8 + tig;
                qf[kt][0] = f2tf32(ap[0]);
                qf[kt][1] = f2tf32(ap[8 * ATS]);
                qf[kt][2] = f2tf32(ap[4]);
                qf[kt][3] = f2tf32(ap[8 * ATS + 4]);
            }
        }

        const float* Kst = KV + cur * KV_STAGE;
        const float* Vst = Kst + 64 * ATS;
        const int kv0 = t * 64;

        // S = Q K^T
        float sa[8][4];
        #pragma unroll
        for (int nt = 0; nt < 8; nt++)
            #pragma unroll
            for (int r = 0; r < 4; r++) sa[nt][r] = 0.f;

        #pragma unroll
        for (int kt = 0; kt < 8; kt++) {
            #pragma unroll
            for (int nt = 0; nt < 8; nt++) {
                const float* bp = Kst + (nt * 8 + gid) * ATS + kt * 8 + tig;
                uint32_t bfr[2] = { f2tf32(bp[0]), f2tf32(bp[4]) };
                mma_tf32(sa[nt], qf[kt], bfr);
            }
        }

        // scale + mask
        const float* mp0 = mask + (size_t)Rg * SEQ + kv0 + 2 * tig;
        const float* mp1 = mp0 + 8 * SEQ;
        #pragma unroll
        for (int nt = 0; nt < 8; nt++) {
            float2 mk0 = *(const float2*)(mp0 + nt * 8);
            float2 mk1 = *(const float2*)(mp1 + nt * 8);
            sa[nt][0] = sa[nt][0] * 0.125f + mk0.x;
            sa[nt][1] = sa[nt][1] * 0.125f + mk0.y;
            sa[nt][2] = sa[nt][2] * 0.125f + mk1.x;
            sa[nt][3] = sa[nt][3] * 0.125f + mk1.y;
        }

        // online softmax over the 64 kv columns (quad = full row)
        float mx0 = -1e30f, mx1 = -1e30f;
        #pragma unroll
        for (int nt = 0; nt < 8; nt++) {
            mx0 = fmaxf(mx0, fmaxf(sa[nt][0], sa[nt][1]));
            mx1 = fmaxf(mx1, fmaxf(sa[nt][2], sa[nt][3]));
        }
        mx0 = fmaxf(mx0, __shfl_xor_sync(0xffffffffu, mx0, 1));
        mx0 = fmaxf(mx0, __shfl_xor_sync(0xffffffffu, mx0, 2));
        mx1 = fmaxf(mx1, __shfl_xor_sync(0xffffffffu, mx1, 1));
        mx1 = fmaxf(mx1, __shfl_xor_sync(0xffffffffu, mx1, 2));

        float mn0 = fmaxf(mrow0, mx0);
        float mn1 = fmaxf(mrow1, mx1);
        float alpha0 = __expf(mrow0 - mn0);
        float alpha1 = __expf(mrow1 - mn1);
        mrow0 = mn0; mrow1 = mn1;

        float sum0 = 0.f, sum1 = 0.f;
        #pragma unroll
        for (int nt = 0; nt < 8; nt++) {
            sa[nt][0] = __expf(sa[nt][0] - mn0);
            sa[nt][1] = __expf(sa[nt][1] - mn0);
            sa[nt][2] = __expf(sa[nt][2] - mn1);
            sa[nt][3] = __expf(sa[nt][3] - mn1);
            sum0 += sa[nt][0] + sa[nt][1];
            sum1 += sa[nt][2] + sa[nt][3];
        }
        sum0 += __shfl_xor_sync(0xffffffffu, sum0, 1);
        sum0 += __shfl_xor_sync(0xffffffffu, sum0, 2);
        sum1 += __shfl_xor_sync(0xffffffffu, sum1, 1);
        sum1 += __shfl_xor_sync(0xffffffffu, sum1, 2);
        lrow0 = lrow0 * alpha0 + sum0;
        lrow1 = lrow1 * alpha1 + sum1;

        #pragma unroll
        for (int nt = 0; nt < 8; nt++) {
            oacc[nt][0] *= alpha0;
            oacc[nt][1] *= alpha0;
            oacc[nt][2] *= alpha1;
            oacc[nt][3] *= alpha1;
        }

        // store P (per-warp private rows)
        float* pr0 = Ps + qrow * ATS + 2 * tig;
        float* pr1 = pr0 + 8 * ATS;
        #pragma unroll
        for (int nt = 0; nt < 8; nt++) {
            *(float2*)(pr0 + nt * 8) = make_float2(sa[nt][0], sa[nt][1]);
            *(float2*)(pr1 + nt * 8) = make_float2(sa[nt][2], sa[nt][3]);
        }
        __syncwarp();

        // O += P V
        #pragma unroll
        for (int kt = 0; kt < 8; kt++) {
            const float* ap = Ps + qrow * ATS + kt * 8 + tig;
            uint32_t pf[4] = { f2tf32(ap[0]), f2tf32(ap[8 * ATS]),
                               f2tf32(ap[4]), f2tf32(ap[8 * ATS + 4]) };
            #pragma unroll
            for (int nt = 0; nt < 8; nt++) {
                const float* bp = Vst + (kt * 8 + tig) * ATS + nt * 8 + gid;
                uint32_t bfr[2] = { f2tf32(bp[0]), f2tf32(bp[4 * ATS]) };
                mma_tf32(oacc[nt], pf, bfr);
            }
        }
        __syncthreads();
    }

    // epilogue
    float inv0 = 1.f / lrow0, inv1 = 1.f / lrow1;
    float* o0 = out + (size_t)(bb * SEQ + Rg) * DIM + h * HD + 2 * tig;
    float* o1 = o0 + 8 * DIM;
    #pragma unroll
    for (int nt = 0; nt < 8; nt++) {
        *(float2*)(o0 + nt * 8) = make_float2(oacc[nt][0] * inv0, oacc[nt][1] * inv0);
        *(float2*)(o1 + nt * 8) = make_float2(oacc[nt][2] * inv1, oacc[nt][3] * inv1);
    }
}

// ---------------------------------------------------------------------------
// Launch
// ---------------------------------------------------------------------------
extern "C" void kernel_launch(void* const* d_in, const int* in_sizes, int n_in,
                              void* d_out, int out_size)
{
    const float* seq   = (const float*)d_in[0];
    const float* amask = (const float*)d_in[1];
    const float* Wqkv  = (const float*)d_in[2];
    const float* W1    = (const float*)d_in[3];
    const float* b1    = (const float*)d_in[4];
    const float* W2    = (const float*)d_in[5];
    const float* b2    = (const float*)d_in[6];
    float* out = (float*)d_out;

    float *qkv, *attn, *hid;
    cudaGetSymbolAddress((void**)&qkv,  g_qkv);
    cudaGetSymbolAddress((void**)&attn, g_attn);
    cudaGetSymbolAddress((void**)&hid,  g_hid);

    cudaFuncSetAttribute(tgemm_kernel<0>, cudaFuncAttributeMaxDynamicSharedMemorySize, GEMM_SMEM_BYTES);
    cudaFuncSetAttribute(tgemm_kernel<1>, cudaFuncAttributeMaxDynamicSharedMemorySize, GEMM_SMEM_BYTES);
    cudaFuncSetAttribute(attn_kernel,     cudaFuncAttributeMaxDynamicSharedMemorySize, ATTN_SMEM_BYTES);

    // 1) QKV projection
    {
        dim3 grid(3 * DIM / 128, ROWS / 128);
        tgemm_kernel<0><<<grid, 256, GEMM_SMEM_BYTES>>>(seq, Wqkv, nullptr, qkv, ROWS, 3 * DIM, DIM);
    }
    // 2) Attention
    {
        dim3 grid(SEQ / 128, HEADS, BSZ);
        attn_kernel<<<grid, 256, ATTN_SMEM_BYTES>>>(qkv, amask, attn);
    }
    // 3) FFN1 + bias + SiLU
    {
        dim3 grid(2 * DIM / 128, ROWS / 128);
        tgemm_kernel<1><<<grid, 256, GEMM_SMEM_BYTES>>>(attn, W1, b1, hid, ROWS, 2 * DIM, DIM);
    }
    // 4) FFN2 + bias
    {
        dim3 grid(DIM / 128, ROWS / 128);
        tgemm_kernel<0><<<grid, 256, GEMM_SMEM_BYTES>>>(hid, W2, b2, out, ROWS, DIM, 2 * DIM);
    }
}

// round 5
// speedup vs baseline: 3.0419x; 1.0759x over previous
#include <cuda_runtime.h>
#include <math.h>
#include <stdint.h>

#define DIM   1024
#define HEADS 16
#define BSZ   2
#define SEQ   2048
#define HD    64
#define ROWS  (BSZ*SEQ)   // 4096

// Scratch (device globals; allocation-free)
__device__ float g_qkv[(size_t)ROWS * 3 * DIM];
__device__ float g_attn[(size_t)ROWS * DIM];
__device__ float g_hid[(size_t)ROWS * 2 * DIM];
// tf32-rounded copies of inputs
__device__ float g_seq_t[(size_t)ROWS * DIM];
__device__ float g_wqkv_t[(size_t)DIM * 3 * DIM];
__device__ float g_w1_t[(size_t)DIM * 2 * DIM];
__device__ float g_w2_t[(size_t)2 * DIM * DIM];

// ---------------------------------------------------------------------------
// helpers
// ---------------------------------------------------------------------------
__device__ __forceinline__ void cp16(void* smem_dst, const void* gmem_src) {
    uint32_t d = (uint32_t)__cvta_generic_to_shared(smem_dst);
    asm volatile("cp.async.cg.shared.global [%0], [%1], 16;\n" :: "r"(d), "l"(gmem_src));
}
#define CP_COMMIT() asm volatile("cp.async.commit_group;\n" ::: "memory")
#define CP_WAIT1()  asm volatile("cp.async.wait_group 1;\n" ::: "memory")

__device__ __forceinline__ float f2tf32f(float x) {
    uint32_t r;
    asm("cvt.rna.tf32.f32 %0, %1;" : "=r"(r) : "f"(x));
    return __uint_as_float(r);
}

__device__ __forceinline__ void mma_tf32(float c[4], const uint32_t a[4], const uint32_t b[2]) {
    asm volatile(
        "mma.sync.aligned.m16n8k8.row.col.f32.tf32.tf32.f32 "
        "{%0,%1,%2,%3}, {%4,%5,%6,%7}, {%8,%9}, {%0,%1,%2,%3};\n"
        : "+f"(c[0]), "+f"(c[1]), "+f"(c[2]), "+f"(c[3])
        : "r"(a[0]), "r"(a[1]), "r"(a[2]), "r"(a[3]), "r"(b[0]), "r"(b[1]));
}

// ---------------------------------------------------------------------------
// tf32 rounding pre-pass: dst[i] = round_tf32(src[i]); n % 1024 == 0
// ---------------------------------------------------------------------------
__global__ __launch_bounds__(256)
void cvt_tf32_kernel(const float* __restrict__ src, float* __restrict__ dst)
{
    size_t i = ((size_t)blockIdx.x * 256 + threadIdx.x) * 4;
    float4 v = *(const float4*)(src + i);
    v.x = f2tf32f(v.x); v.y = f2tf32f(v.y);
    v.z = f2tf32f(v.z); v.w = f2tf32f(v.w);
    *(float4*)(dst + i) = v;
}

// ---------------------------------------------------------------------------
// tf32 tensor-core GEMM: inputs pre-rounded; fragment loads are raw bits.
// ROUND: round output to tf32 (when it feeds another tf32 consumer).
// ---------------------------------------------------------------------------
#define AS_STRIDE 36
#define BS_STRIDE 136
#define A_STAGE (128 * AS_STRIDE)
#define B_STAGE (32 * BS_STRIDE)
#define GEMM_SMEM_BYTES (3 * (A_STAGE + B_STAGE) * 4)  // 107520

__device__ __forceinline__ void gemm_load_tile(
    const float* __restrict__ A, const float* __restrict__ B,
    int K, int N, int bm, int bn, int k0,
    float* Asb, float* Bsb, int tid)
{
    #pragma unroll
    for (int i = 0; i < 4; i++) {
        int id = tid + i * 256;
        int rA = id >> 3, qA = (id & 7) * 4;
        cp16(Asb + rA * AS_STRIDE + qA, A + (size_t)(bm + rA) * K + k0 + qA);
        int rB = id >> 5, qB = (id & 31) * 4;
        cp16(Bsb + rB * BS_STRIDE + qB, B + (size_t)(k0 + rB) * N + bn + qB);
    }
}

template<int ACT, int ROUND>
__global__ __launch_bounds__(256, 2)
void tgemm_kernel(const float* __restrict__ A, const float* __restrict__ B,
                  const float* __restrict__ bias, float* __restrict__ C,
                  int M, int N, int K)
{
    extern __shared__ float smem[];
    float* As = smem;
    float* Bs = smem + 3 * A_STAGE;

    const int tid  = threadIdx.x;
    const int lane = tid & 31;
    const int wid  = tid >> 5;
    const int gid  = lane >> 2;
    const int tig  = lane & 3;
    const int warp_m = wid & 1;
    const int warp_n = wid >> 1;
    const int bm = blockIdx.y * 128;
    const int bn = blockIdx.x * 128;

    float acc[4][4][4];
    #pragma unroll
    for (int mt = 0; mt < 4; mt++)
        #pragma unroll
        for (int nt = 0; nt < 4; nt++)
            #pragma unroll
            for (int r = 0; r < 4; r++) acc[mt][nt][r] = 0.f;

    const int T = K / 32;
    gemm_load_tile(A, B, K, N, bm, bn, 0,  As,           Bs,           tid); CP_COMMIT();
    gemm_load_tile(A, B, K, N, bm, bn, 32, As + A_STAGE, Bs + B_STAGE, tid); CP_COMMIT();

    const int a_row0 = warp_m * 64 + gid;
    const int b_col0 = warp_n * 32 + gid;

    for (int t = 0; t < T; t++) {
        CP_WAIT1();
        __syncthreads();

        int tn = t + 2;
        if (tn < T) {
            gemm_load_tile(A, B, K, N, bm, bn, tn * 32,
                           As + (tn % 3) * A_STAGE, Bs + (tn % 3) * B_STAGE, tid);
        }
        CP_COMMIT();

        const float* Asb = As + (t % 3) * A_STAGE;
        const float* Bsb = Bs + (t % 3) * B_STAGE;

        #pragma unroll
        for (int kq = 0; kq < 4; kq++) {
            const int k0s = kq * 8;
            uint32_t af[4][4];
            #pragma unroll
            for (int mt = 0; mt < 4; mt++) {
                const float* ap = Asb + (a_row0 + mt * 16) * AS_STRIDE + k0s + tig;
                af[mt][0] = __float_as_uint(ap[0]);
                af[mt][1] = __float_as_uint(ap[8 * AS_STRIDE]);
                af[mt][2] = __float_as_uint(ap[4]);
                af[mt][3] = __float_as_uint(ap[8 * AS_STRIDE + 4]);
            }
            uint32_t bf[4][2];
            #pragma unroll
            for (int nt = 0; nt < 4; nt++) {
                const float* bp = Bsb + (k0s + tig) * BS_STRIDE + b_col0 + nt * 8;
                bf[nt][0] = __float_as_uint(bp[0]);
                bf[nt][1] = __float_as_uint(bp[4 * BS_STRIDE]);
            }
            #pragma unroll
            for (int mt = 0; mt < 4; mt++)
                #pragma unroll
                for (int nt = 0; nt < 4; nt++)
                    mma_tf32(acc[mt][nt], af[mt], bf[nt]);
        }
    }

    #pragma unroll
    for (int mt = 0; mt < 4; mt++) {
        const int r0 = bm + warp_m * 64 + mt * 16 + gid;
        #pragma unroll
        for (int nt = 0; nt < 4; nt++) {
            const int c0 = bn + warp_n * 32 + nt * 8 + tig * 2;
            float b0 = 0.f, b1 = 0.f;
            if (bias) { b0 = bias[c0]; b1 = bias[c0 + 1]; }
            float v0 = acc[mt][nt][0] + b0;
            float v1 = acc[mt][nt][1] + b1;
            float v2 = acc[mt][nt][2] + b0;
            float v3 = acc[mt][nt][3] + b1;
            if (ACT == 1) {
                v0 = v0 / (1.f + __expf(-v0));
                v1 = v1 / (1.f + __expf(-v1));
                v2 = v2 / (1.f + __expf(-v2));
                v3 = v3 / (1.f + __expf(-v3));
            }
            if (ROUND) {
                v0 = f2tf32f(v0); v1 = f2tf32f(v1);
                v2 = f2tf32f(v2); v3 = f2tf32f(v3);
            }
            *(float2*)(C + (size_t)r0 * N + c0)       = make_float2(v0, v1);
            *(float2*)(C + (size_t)(r0 + 8) * N + c0) = make_float2(v2, v3);
        }
    }
}

// ---------------------------------------------------------------------------
// tf32 tensor-core flash attention. qkv already tf32-rounded -> raw fragment
// loads. P rounded once at smem store. Output rounded (feeds FFN1).
// ---------------------------------------------------------------------------
#define ATS 68
#define KV_STAGE (2 * 64 * ATS)
#define ATTN_SMEM_FLOATS (128 * ATS + 2 * KV_STAGE)
#define ATTN_SMEM_BYTES  (ATTN_SMEM_FLOATS * 4)   // 104448

__device__ __forceinline__ void attn_load_kv(
    const float* kbase, const float* vbase, int kv0,
    float* Kst, float* Vst, int tid)
{
    #pragma unroll
    for (int i = 0; i < 4; i++) {
        int c = tid + i * 256;
        int r = c >> 4, q = (c & 15) * 4;
        cp16(Kst + r * ATS + q, kbase + (size_t)(kv0 + r) * (3 * DIM) + q);
        cp16(Vst + r * ATS + q, vbase + (size_t)(kv0 + r) * (3 * DIM) + q);
    }
}

__global__ __launch_bounds__(256)
void attn_kernel(const float* __restrict__ qkv,
                 const float* __restrict__ mask,
                 float* __restrict__ out)
{
    extern __shared__ float smem[];
    float* Ps = smem;                 // 128 x 68 : Q staging, then P
    float* KV = smem + 128 * ATS;

    const int tid  = threadIdx.x;
    const int lane = tid & 31;
    const int w    = tid >> 5;
    const int gid  = lane >> 2;
    const int tig  = lane & 3;
    const int bb = blockIdx.z, h = blockIdx.y;
    const int q0 = blockIdx.x * 128;
    const size_t ldq = 3 * DIM;

    const float* qbase = qkv + (size_t)(bb * SEQ + q0) * ldq + h * HD;
    const float* kbase = qkv + (size_t)(bb * SEQ) * ldq + DIM + h * HD;
    const float* vbase = kbase + DIM;

    #pragma unroll
    for (int i = 0; i < 8; i++) {
        int c = tid + i * 256;
        int r = c >> 4, q = (c & 15) * 4;
        cp16(Ps + r * ATS + q, qbase + (size_t)r * ldq + q);
    }
    attn_load_kv(kbase, vbase, 0, KV, KV + 64 * ATS, tid);
    CP_COMMIT();

    uint32_t qf[8][4];
    float oacc[8][4];
    #pragma unroll
    for (int nt = 0; nt < 8; nt++)
        #pragma unroll
        for (int r = 0; r < 4; r++) oacc[nt][r] = 0.f;
    float mrow0 = -1e30f, mrow1 = -1e30f, lrow0 = 0.f, lrow1 = 0.f;

    const int qrow = w * 16 + gid;
    const int Rg = q0 + qrow;

    const int NT = SEQ / 64;
    for (int t = 0; t < NT; t++) {
        const int cur = t & 1;
        if (t + 1 < NT) {
            float* Kn = KV + ((t + 1) & 1) * KV_STAGE;
            attn_load_kv(kbase, vbase, (t + 1) * 64, Kn, Kn + 64 * ATS, tid);
        }
        CP_COMMIT();
        CP_WAIT1();
        __syncthreads();

        if (t == 0) {
            #pragma unroll
            for (int kt = 0; kt < 8; kt++) {
                const float* ap = Ps + qrow * ATS + kt * 8 + tig;
                qf[kt][0] = __float_as_uint(ap[0]);
                qf[kt][1] = __float_as_uint(ap[8 * ATS]);
                qf[kt][2] = __float_as_uint(ap[4]);
                qf[kt][3] = __float_as_uint(ap[8 * ATS + 4]);
            }
        }

        const float* Kst = KV + cur * KV_STAGE;
        const float* Vst = Kst + 64 * ATS;
        const int kv0 = t * 64;

        float sa[8][4];
        #pragma unroll
        for (int nt = 0; nt < 8; nt++)
            #pragma unroll
            for (int r = 0; r < 4; r++) sa[nt][r] = 0.f;

        #pragma unroll
        for (int kt = 0; kt < 8; kt++) {
            #pragma unroll
            for (int nt = 0; nt < 8; nt++) {
                const float* bp = Kst + (nt * 8 + gid) * ATS + kt * 8 + tig;
                uint32_t bfr[2] = { __float_as_uint(bp[0]), __float_as_uint(bp[4]) };
                mma_tf32(sa[nt], qf[kt], bfr);
            }
        }

        const float* mp0 = mask + (size_t)Rg * SEQ + kv0 + 2 * tig;
        const float* mp1 = mp0 + 8 * SEQ;
        #pragma unroll
        for (int nt = 0; nt < 8; nt++) {
            float2 mk0 = *(const float2*)(mp0 + nt * 8);
            float2 mk1 = *(const float2*)(mp1 + nt * 8);
            sa[nt][0] = sa[nt][0] * 0.125f + mk0.x;
            sa[nt][1] = sa[nt][1] * 0.125f + mk0.y;
            sa[nt][2] = sa[nt][2] * 0.125f + mk1.x;
            sa[nt][3] = sa[nt][3] * 0.125f + mk1.y;
        }

        float mx0 = -1e30f, mx1 = -1e30f;
        #pragma unroll
        for (int nt = 0; nt < 8; nt++) {
            mx0 = fmaxf(mx0, fmaxf(sa[nt][0], sa[nt][1]));
            mx1 = fmaxf(mx1, fmaxf(sa[nt][2], sa[nt][3]));
        }
        mx0 = fmaxf(mx0, __shfl_xor_sync(0xffffffffu, mx0, 1));
        mx0 = fmaxf(mx0, __shfl_xor_sync(0xffffffffu, mx0, 2));
        mx1 = fmaxf(mx1, __shfl_xor_sync(0xffffffffu, mx1, 1));
        mx1 = fmaxf(mx1, __shfl_xor_sync(0xffffffffu, mx1, 2));

        float mn0 = fmaxf(mrow0, mx0);
        float mn1 = fmaxf(mrow1, mx1);
        float alpha0 = __expf(mrow0 - mn0);
        float alpha1 = __expf(mrow1 - mn1);
        mrow0 = mn0; mrow1 = mn1;

        float sum0 = 0.f, sum1 = 0.f;
        #pragma unroll
        for (int nt = 0; nt < 8; nt++) {
            sa[nt][0] = __expf(sa[nt][0] - mn0);
            sa[nt][1] = __expf(sa[nt][1] - mn0);
            sa[nt][2] = __expf(sa[nt][2] - mn1);
            sa[nt][3] = __expf(sa[nt][3] - mn1);
            sum0 += sa[nt][0] + sa[nt][1];
            sum1 += sa[nt][2] + sa[nt][3];
        }
        sum0 += __shfl_xor_sync(0xffffffffu, sum0, 1);
        sum0 += __shfl_xor_sync(0xffffffffu, sum0, 2);
        sum1 += __shfl_xor_sync(0xffffffffu, sum1, 1);
        sum1 += __shfl_xor_sync(0xffffffffu, sum1, 2);
        lrow0 = lrow0 * alpha0 + sum0;
        lrow1 = lrow1 * alpha1 + sum1;

        #pragma unroll
        for (int nt = 0; nt < 8; nt++) {
            oacc[nt][0] *= alpha0;
            oacc[nt][1] *= alpha0;
            oacc[nt][2] *= alpha1;
            oacc[nt][3] *= alpha1;
        }

        // store P rounded to tf32 (per-warp private rows)
        float* pr0 = Ps + qrow * ATS + 2 * tig;
        float* pr1 = pr0 + 8 * ATS;
        #pragma unroll
        for (int nt = 0; nt < 8; nt++) {
            *(float2*)(pr0 + nt * 8) = make_float2(f2tf32f(sa[nt][0]), f2tf32f(sa[nt][1]));
            *(float2*)(pr1 + nt * 8) = make_float2(f2tf32f(sa[nt][2]), f2tf32f(sa[nt][3]));
        }
        __syncwarp();

        #pragma unroll
        for (int kt = 0; kt < 8; kt++) {
            const float* ap = Ps + qrow * ATS + kt * 8 + tig;
            uint32_t pf[4] = { __float_as_uint(ap[0]), __float_as_uint(ap[8 * ATS]),
                               __float_as_uint(ap[4]), __float_as_uint(ap[8 * ATS + 4]) };
            #pragma unroll
            for (int nt = 0; nt < 8; nt++) {
                const float* bp = Vst + (kt * 8 + tig) * ATS + nt * 8 + gid;
                uint32_t bfr[2] = { __float_as_uint(bp[0]), __float_as_uint(bp[4 * ATS]) };
                mma_tf32(oacc[nt], pf, bfr);
            }
        }
        __syncthreads();
    }

    float inv0 = 1.f / lrow0, inv1 = 1.f / lrow1;
    float* o0 = out + (size_t)(bb * SEQ + Rg) * DIM + h * HD + 2 * tig;
    float* o1 = o0 + 8 * DIM;
    #pragma unroll
    for (int nt = 0; nt < 8; nt++) {
        *(float2*)(o0 + nt * 8) = make_float2(f2tf32f(oacc[nt][0] * inv0),
                                              f2tf32f(oacc[nt][1] * inv0));
        *(float2*)(o1 + nt * 8) = make_float2(f2tf32f(oacc[nt][2] * inv1),
                                              f2tf32f(oacc[nt][3] * inv1));
    }
}

// ---------------------------------------------------------------------------
// Launch
// ---------------------------------------------------------------------------
extern "C" void kernel_launch(void* const* d_in, const int* in_sizes, int n_in,
                              void* d_out, int out_size)
{
    const float* seq   = (const float*)d_in[0];
    const float* amask = (const float*)d_in[1];
    const float* Wqkv  = (const float*)d_in[2];
    const float* W1    = (const float*)d_in[3];
    const float* b1    = (const float*)d_in[4];
    const float* W2    = (const float*)d_in[5];
    const float* b2    = (const float*)d_in[6];
    float* out = (float*)d_out;

    float *qkv, *attn, *hid, *seq_t, *wqkv_t, *w1_t, *w2_t;
    cudaGetSymbolAddress((void**)&qkv,    g_qkv);
    cudaGetSymbolAddress((void**)&attn,   g_attn);
    cudaGetSymbolAddress((void**)&hid,    g_hid);
    cudaGetSymbolAddress((void**)&seq_t,  g_seq_t);
    cudaGetSymbolAddress((void**)&wqkv_t, g_wqkv_t);
    cudaGetSymbolAddress((void**)&w1_t,   g_w1_t);
    cudaGetSymbolAddress((void**)&w2_t,   g_w2_t);

    cudaFuncSetAttribute((const void*)tgemm_kernel<0,1>, cudaFuncAttributeMaxDynamicSharedMemorySize, GEMM_SMEM_BYTES);
    cudaFuncSetAttribute((const void*)tgemm_kernel<1,1>, cudaFuncAttributeMaxDynamicSharedMemorySize, GEMM_SMEM_BYTES);
    cudaFuncSetAttribute((const void*)tgemm_kernel<0,0>, cudaFuncAttributeMaxDynamicSharedMemorySize, GEMM_SMEM_BYTES);
    cudaFuncSetAttribute((const void*)attn_kernel,       cudaFuncAttributeMaxDynamicSharedMemorySize, ATTN_SMEM_BYTES);

    // 0) tf32 pre-rounding of inputs
    cvt_tf32_kernel<<<(ROWS * DIM) / 1024, 256>>>(seq, seq_t);
    cvt_tf32_kernel<<<(DIM * 3 * DIM) / 1024, 256>>>(Wqkv, wqkv_t);
    cvt_tf32_kernel<<<(DIM * 2 * DIM) / 1024, 256>>>(W1, w1_t);
    cvt_tf32_kernel<<<(2 * DIM * DIM) / 1024, 256>>>(W2, w2_t);

    // 1) QKV projection (output rounded: feeds attention)
    {
        dim3 grid(3 * DIM / 128, ROWS / 128);
        tgemm_kernel<0,1><<<grid, 256, GEMM_SMEM_BYTES>>>(seq_t, wqkv_t, nullptr, qkv, ROWS, 3 * DIM, DIM);
    }
    // 2) Attention (output rounded: feeds FFN1)
    {
        dim3 grid(SEQ / 128, HEADS, BSZ);
        attn_kernel<<<grid, 256, ATTN_SMEM_BYTES>>>(qkv, amask, attn);
    }
    // 3) FFN1 + bias + SiLU (output rounded: feeds FFN2)
    {
        dim3 grid(2 * DIM / 128, ROWS / 128);
        tgemm_kernel<1,1><<<grid, 256, GEMM_SMEM_BYTES>>>(attn, w1_t, b1, hid, ROWS, 2 * DIM, DIM);
    }
    // 4) FFN2 + bias (final output: full fp32)
    {
        dim3 grid(DIM / 128, ROWS / 128);
        tgemm_kernel<0,0><<<grid, 256, GEMM_SMEM_BYTES>>>(hid, w2_t, b2, out, ROWS, DIM, 2 * DIM);
    }
}

// round 6
// speedup vs baseline: 3.3202x; 1.0915x over previous
#include <cuda_runtime.h>
#include <math.h>
#include <stdint.h>

#define DIM   1024
#define HEADS 16
#define BSZ   2
#define SEQ   2048
#define HD    64
#define ROWS  (BSZ*SEQ)   // 4096

// Scratch (device globals; allocation-free)
__device__ float g_qkv[(size_t)ROWS * 3 * DIM];
__device__ float g_attn[(size_t)ROWS * DIM];
__device__ float g_hid[(size_t)ROWS * 2 * DIM];
// tf32-rounded copies of inputs
__device__ float g_seq_t[(size_t)ROWS * DIM];
__device__ float g_wqkv_t[(size_t)DIM * 3 * DIM];
__device__ float g_w1_t[(size_t)DIM * 2 * DIM];
__device__ float g_w2_t[(size_t)2 * DIM * DIM];

// ---------------------------------------------------------------------------
// helpers
// ---------------------------------------------------------------------------
__device__ __forceinline__ void cp16(void* smem_dst, const void* gmem_src) {
    uint32_t d = (uint32_t)__cvta_generic_to_shared(smem_dst);
    asm volatile("cp.async.cg.shared.global [%0], [%1], 16;\n" :: "r"(d), "l"(gmem_src));
}
#define CP_COMMIT() asm volatile("cp.async.commit_group;\n" ::: "memory")
#define CP_WAIT1()  asm volatile("cp.async.wait_group 1;\n" ::: "memory")

__device__ __forceinline__ float f2tf32f(float x) {
    uint32_t r;
    asm("cvt.rna.tf32.f32 %0, %1;" : "=r"(r) : "f"(x));
    return __uint_as_float(r);
}

__device__ __forceinline__ void mma_tf32(float c[4], const uint32_t a[4], const uint32_t b[2]) {
    asm volatile(
        "mma.sync.aligned.m16n8k8.row.col.f32.tf32.tf32.f32 "
        "{%0,%1,%2,%3}, {%4,%5,%6,%7}, {%8,%9}, {%0,%1,%2,%3};\n"
        : "+f"(c[0]), "+f"(c[1]), "+f"(c[2]), "+f"(c[3])
        : "r"(a[0]), "r"(a[1]), "r"(a[2]), "r"(a[3]), "r"(b[0]), "r"(b[1]));
}

// ---------------------------------------------------------------------------
// tf32 rounding pre-pass
// ---------------------------------------------------------------------------
__global__ __launch_bounds__(256)
void cvt_tf32_kernel(const float* __restrict__ src, float* __restrict__ dst)
{
    size_t i = ((size_t)blockIdx.x * 256 + threadIdx.x) * 4;
    float4 v = *(const float4*)(src + i);
    v.x = f2tf32f(v.x); v.y = f2tf32f(v.y);
    v.z = f2tf32f(v.z); v.w = f2tf32f(v.w);
    *(float4*)(dst + i) = v;
}

// ---------------------------------------------------------------------------
// tf32 tensor-core GEMM (inputs pre-rounded; raw fragment loads)
// ---------------------------------------------------------------------------
#define AS_STRIDE 36
#define BS_STRIDE 136
#define A_STAGE (128 * AS_STRIDE)
#define B_STAGE (32 * BS_STRIDE)
#define GEMM_SMEM_BYTES (3 * (A_STAGE + B_STAGE) * 4)  // 107520

__device__ __forceinline__ void gemm_load_tile(
    const float* __restrict__ A, const float* __restrict__ B,
    int K, int N, int bm, int bn, int k0,
    float* Asb, float* Bsb, int tid)
{
    #pragma unroll
    for (int i = 0; i < 4; i++) {
        int id = tid + i * 256;
        int rA = id >> 3, qA = (id & 7) * 4;
        cp16(Asb + rA * AS_STRIDE + qA, A + (size_t)(bm + rA) * K + k0 + qA);
        int rB = id >> 5, qB = (id & 31) * 4;
        cp16(Bsb + rB * BS_STRIDE + qB, B + (size_t)(k0 + rB) * N + bn + qB);
    }
}

template<int ACT, int ROUND>
__global__ __launch_bounds__(256, 2)
void tgemm_kernel(const float* __restrict__ A, const float* __restrict__ B,
                  const float* __restrict__ bias, float* __restrict__ C,
                  int M, int N, int K)
{
    extern __shared__ float smem[];
    float* As = smem;
    float* Bs = smem + 3 * A_STAGE;

    const int tid  = threadIdx.x;
    const int lane = tid & 31;
    const int wid  = tid >> 5;
    const int gid  = lane >> 2;
    const int tig  = lane & 3;
    const int warp_m = wid & 1;
    const int warp_n = wid >> 1;
    const int bm = blockIdx.y * 128;
    const int bn = blockIdx.x * 128;

    float acc[4][4][4];
    #pragma unroll
    for (int mt = 0; mt < 4; mt++)
        #pragma unroll
        for (int nt = 0; nt < 4; nt++)
            #pragma unroll
            for (int r = 0; r < 4; r++) acc[mt][nt][r] = 0.f;

    const int T = K / 32;
    gemm_load_tile(A, B, K, N, bm, bn, 0,  As,           Bs,           tid); CP_COMMIT();
    gemm_load_tile(A, B, K, N, bm, bn, 32, As + A_STAGE, Bs + B_STAGE, tid); CP_COMMIT();

    const int a_row0 = warp_m * 64 + gid;
    const int b_col0 = warp_n * 32 + gid;

    for (int t = 0; t < T; t++) {
        CP_WAIT1();
        __syncthreads();

        int tn = t + 2;
        if (tn < T) {
            gemm_load_tile(A, B, K, N, bm, bn, tn * 32,
                           As + (tn % 3) * A_STAGE, Bs + (tn % 3) * B_STAGE, tid);
        }
        CP_COMMIT();

        const float* Asb = As + (t % 3) * A_STAGE;
        const float* Bsb = Bs + (t % 3) * B_STAGE;

        #pragma unroll
        for (int kq = 0; kq < 4; kq++) {
            const int k0s = kq * 8;
            uint32_t af[4][4];
            #pragma unroll
            for (int mt = 0; mt < 4; mt++) {
                const float* ap = Asb + (a_row0 + mt * 16) * AS_STRIDE + k0s + tig;
                af[mt][0] = __float_as_uint(ap[0]);
                af[mt][1] = __float_as_uint(ap[8 * AS_STRIDE]);
                af[mt][2] = __float_as_uint(ap[4]);
                af[mt][3] = __float_as_uint(ap[8 * AS_STRIDE + 4]);
            }
            uint32_t bf[4][2];
            #pragma unroll
            for (int nt = 0; nt < 4; nt++) {
                const float* bp = Bsb + (k0s + tig) * BS_STRIDE + b_col0 + nt * 8;
                bf[nt][0] = __float_as_uint(bp[0]);
                bf[nt][1] = __float_as_uint(bp[4 * BS_STRIDE]);
            }
            #pragma unroll
            for (int mt = 0; mt < 4; mt++)
                #pragma unroll
                for (int nt = 0; nt < 4; nt++)
                    mma_tf32(acc[mt][nt], af[mt], bf[nt]);
        }
    }

    #pragma unroll
    for (int mt = 0; mt < 4; mt++) {
        const int r0 = bm + warp_m * 64 + mt * 16 + gid;
        #pragma unroll
        for (int nt = 0; nt < 4; nt++) {
            const int c0 = bn + warp_n * 32 + nt * 8 + tig * 2;
            float b0 = 0.f, b1 = 0.f;
            if (bias) { b0 = bias[c0]; b1 = bias[c0 + 1]; }
            float v0 = acc[mt][nt][0] + b0;
            float v1 = acc[mt][nt][1] + b1;
            float v2 = acc[mt][nt][2] + b0;
            float v3 = acc[mt][nt][3] + b1;
            if (ACT == 1) {
                v0 = v0 / (1.f + __expf(-v0));
                v1 = v1 / (1.f + __expf(-v1));
                v2 = v2 / (1.f + __expf(-v2));
                v3 = v3 / (1.f + __expf(-v3));
            }
            if (ROUND) {
                v0 = f2tf32f(v0); v1 = f2tf32f(v1);
                v2 = f2tf32f(v2); v3 = f2tf32f(v3);
            }
            *(float2*)(C + (size_t)r0 * N + c0)       = make_float2(v0, v1);
            *(float2*)(C + (size_t)(r0 + 8) * N + c0) = make_float2(v2, v3);
        }
    }
}

// ---------------------------------------------------------------------------
// tf32 tensor-core flash attention, now 2 blocks/SM.
// ---------------------------------------------------------------------------
#define ATS 68
#define KV_STAGE (2 * 64 * ATS)
#define ATTN_SMEM_FLOATS (128 * ATS + 2 * KV_STAGE)
#define ATTN_SMEM_BYTES  (ATTN_SMEM_FLOATS * 4)   // 104448

__device__ __forceinline__ void attn_load_kv(
    const float* kbase, const float* vbase, int kv0,
    float* Kst, float* Vst, int tid)
{
    #pragma unroll
    for (int i = 0; i < 4; i++) {
        int c = tid + i * 256;
        int r = c >> 4, q = (c & 15) * 4;
        cp16(Kst + r * ATS + q, kbase + (size_t)(kv0 + r) * (3 * DIM) + q);
        cp16(Vst + r * ATS + q, vbase + (size_t)(kv0 + r) * (3 * DIM) + q);
    }
}

__global__ __launch_bounds__(256, 2)
void attn_kernel(const float* __restrict__ qkv,
                 const float* __restrict__ mask,
                 float* __restrict__ out)
{
    extern __shared__ float smem[];
    float* Ps = smem;                 // 128 x 68 : Q staging, then P
    float* KV = smem + 128 * ATS;

    const int tid  = threadIdx.x;
    const int lane = tid & 31;
    const int w    = tid >> 5;
    const int gid  = lane >> 2;
    const int tig  = lane & 3;
    const int bb = blockIdx.z, h = blockIdx.y;
    const int q0 = blockIdx.x * 128;
    const size_t ldq = 3 * DIM;

    const float* qbase = qkv + (size_t)(bb * SEQ + q0) * ldq + h * HD;
    const float* kbase = qkv + (size_t)(bb * SEQ) * ldq + DIM + h * HD;
    const float* vbase = kbase + DIM;

    #pragma unroll
    for (int i = 0; i < 8; i++) {
        int c = tid + i * 256;
        int r = c >> 4, q = (c & 15) * 4;
        cp16(Ps + r * ATS + q, qbase + (size_t)r * ldq + q);
    }
    attn_load_kv(kbase, vbase, 0, KV, KV + 64 * ATS, tid);
    CP_COMMIT();

    uint32_t qf[8][4];
    float oacc[8][4];
    #pragma unroll
    for (int nt = 0; nt < 8; nt++)
        #pragma unroll
        for (int r = 0; r < 4; r++) oacc[nt][r] = 0.f;
    float mrow0 = -1e30f, mrow1 = -1e30f, lrow0 = 0.f, lrow1 = 0.f;

    const int qrow = w * 16 + gid;
    const int Rg = q0 + qrow;

    const int NT = SEQ / 64;
    for (int t = 0; t < NT; t++) {
        const int cur = t & 1;
        if (t + 1 < NT) {
            float* Kn = KV + ((t + 1) & 1) * KV_STAGE;
            attn_load_kv(kbase, vbase, (t + 1) * 64, Kn, Kn + 64 * ATS, tid);
        }
        CP_COMMIT();
        CP_WAIT1();
        __syncthreads();

        if (t == 0) {
            #pragma unroll
            for (int kt = 0; kt < 8; kt++) {
                const float* ap = Ps + qrow * ATS + kt * 8 + tig;
                qf[kt][0] = __float_as_uint(ap[0]);
                qf[kt][1] = __float_as_uint(ap[8 * ATS]);
                qf[kt][2] = __float_as_uint(ap[4]);
                qf[kt][3] = __float_as_uint(ap[8 * ATS + 4]);
            }
        }

        const float* Kst = KV + cur * KV_STAGE;
        const float* Vst = Kst + 64 * ATS;
        const int kv0 = t * 64;

        float sa[8][4];
        #pragma unroll
        for (int nt = 0; nt < 8; nt++)
            #pragma unroll
            for (int r = 0; r < 4; r++) sa[nt][r] = 0.f;

        #pragma unroll
        for (int kt = 0; kt < 8; kt++) {
            #pragma unroll
            for (int nt = 0; nt < 8; nt++) {
                const float* bp = Kst + (nt * 8 + gid) * ATS + kt * 8 + tig;
                uint32_t bfr[2] = { __float_as_uint(bp[0]), __float_as_uint(bp[4]) };
                mma_tf32(sa[nt], qf[kt], bfr);
            }
        }

        const float* mp0 = mask + (size_t)Rg * SEQ + kv0 + 2 * tig;
        const float* mp1 = mp0 + 8 * SEQ;
        #pragma unroll
        for (int nt = 0; nt < 8; nt++) {
            float2 mk0 = *(const float2*)(mp0 + nt * 8);
            float2 mk1 = *(const float2*)(mp1 + nt * 8);
            sa[nt][0] = sa[nt][0] * 0.125f + mk0.x;
            sa[nt][1] = sa[nt][1] * 0.125f + mk0.y;
            sa[nt][2] = sa[nt][2] * 0.125f + mk1.x;
            sa[nt][3] = sa[nt][3] * 0.125f + mk1.y;
        }

        float mx0 = -1e30f, mx1 = -1e30f;
        #pragma unroll
        for (int nt = 0; nt < 8; nt++) {
            mx0 = fmaxf(mx0, fmaxf(sa[nt][0], sa[nt][1]));
            mx1 = fmaxf(mx1, fmaxf(sa[nt][2], sa[nt][3]));
        }
        mx0 = fmaxf(mx0, __shfl_xor_sync(0xffffffffu, mx0, 1));
        mx0 = fmaxf(mx0, __shfl_xor_sync(0xffffffffu, mx0, 2));
        mx1 = fmaxf(mx1, __shfl_xor_sync(0xffffffffu, mx1, 1));
        mx1 = fmaxf(mx1, __shfl_xor_sync(0xffffffffu, mx1, 2));

        float mn0 = fmaxf(mrow0, mx0);
        float mn1 = fmaxf(mrow1, mx1);
        float alpha0 = __expf(mrow0 - mn0);
        float alpha1 = __expf(mrow1 - mn1);
        mrow0 = mn0; mrow1 = mn1;

        float sum0 = 0.f, sum1 = 0.f;
        #pragma unroll
        for (int nt = 0; nt < 8; nt++) {
            sa[nt][0] = __expf(sa[nt][0] - mn0);
            sa[nt][1] = __expf(sa[nt][1] - mn0);
            sa[nt][2] = __expf(sa[nt][2] - mn1);
            sa[nt][3] = __expf(sa[nt][3] - mn1);
            sum0 += sa[nt][0] + sa[nt][1];
            sum1 += sa[nt][2] + sa[nt][3];
        }
        sum0 += __shfl_xor_sync(0xffffffffu, sum0, 1);
        sum0 += __shfl_xor_sync(0xffffffffu, sum0, 2);
        sum1 += __shfl_xor_sync(0xffffffffu, sum1, 1);
        sum1 += __shfl_xor_sync(0xffffffffu, sum1, 2);
        lrow0 = lrow0 * alpha0 + sum0;
        lrow1 = lrow1 * alpha1 + sum1;

        #pragma unroll
        for (int nt = 0; nt < 8; nt++) {
            oacc[nt][0] *= alpha0;
            oacc[nt][1] *= alpha0;
            oacc[nt][2] *= alpha1;
            oacc[nt][3] *= alpha1;
        }

        float* pr0 = Ps + qrow * ATS + 2 * tig;
        float* pr1 = pr0 + 8 * ATS;
        #pragma unroll
        for (int nt = 0; nt < 8; nt++) {
            *(float2*)(pr0 + nt * 8) = make_float2(f2tf32f(sa[nt][0]), f2tf32f(sa[nt][1]));
            *(float2*)(pr1 + nt * 8) = make_float2(f2tf32f(sa[nt][2]), f2tf32f(sa[nt][3]));
        }
        __syncwarp();

        #pragma unroll
        for (int kt = 0; kt < 8; kt++) {
            const float* ap = Ps + qrow * ATS + kt * 8 + tig;
            uint32_t pf[4] = { __float_as_uint(ap[0]), __float_as_uint(ap[8 * ATS]),
                               __float_as_uint(ap[4]), __float_as_uint(ap[8 * ATS + 4]) };
            #pragma unroll
            for (int nt = 0; nt < 8; nt++) {
                const float* bp = Vst + (kt * 8 + tig) * ATS + nt * 8 + gid;
                uint32_t bfr[2] = { __float_as_uint(bp[0]), __float_as_uint(bp[4 * ATS]) };
                mma_tf32(oacc[nt], pf, bfr);
            }
        }
        __syncthreads();
    }

    float inv0 = 1.f / lrow0, inv1 = 1.f / lrow1;
    float* o0 = out + (size_t)(bb * SEQ + Rg) * DIM + h * HD + 2 * tig;
    float* o1 = o0 + 8 * DIM;
    #pragma unroll
    for (int nt = 0; nt < 8; nt++) {
        *(float2*)(o0 + nt * 8) = make_float2(f2tf32f(oacc[nt][0] * inv0),
                                              f2tf32f(oacc[nt][1] * inv0));
        *(float2*)(o1 + nt * 8) = make_float2(f2tf32f(oacc[nt][2] * inv1),
                                              f2tf32f(oacc[nt][3] * inv1));
    }
}

// ---------------------------------------------------------------------------
// Launch
// ---------------------------------------------------------------------------
extern "C" void kernel_launch(void* const* d_in, const int* in_sizes, int n_in,
                              void* d_out, int out_size)
{
    const float* seq   = (const float*)d_in[0];
    const float* amask = (const float*)d_in[1];
    const float* Wqkv  = (const float*)d_in[2];
    const float* W1    = (const float*)d_in[3];
    const float* b1    = (const float*)d_in[4];
    const float* W2    = (const float*)d_in[5];
    const float* b2    = (const float*)d_in[6];
    float* out = (float*)d_out;

    float *qkv, *attn, *hid, *seq_t, *wqkv_t, *w1_t, *w2_t;
    cudaGetSymbolAddress((void**)&qkv,    g_qkv);
    cudaGetSymbolAddress((void**)&attn,   g_attn);
    cudaGetSymbolAddress((void**)&hid,    g_hid);
    cudaGetSymbolAddress((void**)&seq_t,  g_seq_t);
    cudaGetSymbolAddress((void**)&wqkv_t, g_wqkv_t);
    cudaGetSymbolAddress((void**)&w1_t,   g_w1_t);
    cudaGetSymbolAddress((void**)&w2_t,   g_w2_t);

    cudaFuncSetAttribute((const void*)tgemm_kernel<0,1>, cudaFuncAttributeMaxDynamicSharedMemorySize, GEMM_SMEM_BYTES);
    cudaFuncSetAttribute((const void*)tgemm_kernel<1,1>, cudaFuncAttributeMaxDynamicSharedMemorySize, GEMM_SMEM_BYTES);
    cudaFuncSetAttribute((const void*)tgemm_kernel<0,0>, cudaFuncAttributeMaxDynamicSharedMemorySize, GEMM_SMEM_BYTES);
    cudaFuncSetAttribute((const void*)attn_kernel,       cudaFuncAttributeMaxDynamicSharedMemorySize, ATTN_SMEM_BYTES);

    // 0) tf32 pre-rounding of inputs
    cvt_tf32_kernel<<<(ROWS * DIM) / 1024, 256>>>(seq, seq_t);
    cvt_tf32_kernel<<<(DIM * 3 * DIM) / 1024, 256>>>(Wqkv, wqkv_t);
    cvt_tf32_kernel<<<(DIM * 2 * DIM) / 1024, 256>>>(W1, w1_t);
    cvt_tf32_kernel<<<(2 * DIM * DIM) / 1024, 256>>>(W2, w2_t);

    // 1) QKV projection (output rounded: feeds attention)
    {
        dim3 grid(3 * DIM / 128, ROWS / 128);
        tgemm_kernel<0,1><<<grid, 256, GEMM_SMEM_BYTES>>>(seq_t, wqkv_t, nullptr, qkv, ROWS, 3 * DIM, DIM);
    }
    // 2) Attention (output rounded: feeds FFN1)
    {
        dim3 grid(SEQ / 128, HEADS, BSZ);
        attn_kernel<<<grid, 256, ATTN_SMEM_BYTES>>>(qkv, amask, attn);
    }
    // 3) FFN1 + bias + SiLU (output rounded: feeds FFN2)
    {
        dim3 grid(2 * DIM / 128, ROWS / 128);
        tgemm_kernel<1,1><<<grid, 256, GEMM_SMEM_BYTES>>>(attn, w1_t, b1, hid, ROWS, 2 * DIM, DIM);
    }
    // 4) FFN2 + bias (final output: full fp32)
    {
        dim3 grid(DIM / 128, ROWS / 128);
        tgemm_kernel<0,0><<<grid, 256, GEMM_SMEM_BYTES>>>(hid, w2_t, b2, out, ROWS, DIM, 2 * DIM);
    }
}